// round 12
// baseline (speedup 1.0000x reference)
#include <cuda_runtime.h>
#include <cuda_fp16.h>
#include <float.h>
#include <stdint.h>

#define NMAX 4096
#define DIMK 256              // fp32 features per row
#define NSC  4                // 16KB sub-chunks per 128-row block (64 cols each)
#define NCH  4                // 64-kcol chunks per 128x128 tile
#define NSTG 4                // smem pipeline stages (== chunks/tile)
#define NTHR 512
#define SUB_BYTES 16384       // one 128x64 fp16 sub-chunk, pre-swizzled

// ---------------- device scratch (no allocs allowed) ----------------
__device__ int   g_posmax[NMAX];
__device__ int   g_negmin[NMAX];
__device__ float g_xx[NMAX];
__device__ int   g_lab[NMAX];
__device__ int   g_done;
// chunk-major pre-swizzled fp16 features:
// block b = row/128, sub-chunk c = col/64 -> contiguous 16KB at ((b*4+c)<<14)
__device__ __align__(16) __half g_f16s[NMAX * DIMK];

// ---------------- PTX helpers (sm_90-baseline ISA) ----------------
__device__ __forceinline__ uint32_t s2u(const void* p) {
    uint32_t a;
    asm("{ .reg .u64 t; cvta.to.shared.u64 t, %1; cvt.u32.u64 %0, t; }" : "=r"(a) : "l"(p));
    return a;
}
#define MBAR_INIT(a, c) asm volatile("mbarrier.init.shared.b64 [%0], %1;" :: "r"(a), "r"(c) : "memory")
#define MBAR_EXPECT_TX(a, b) asm volatile("mbarrier.arrive.expect_tx.shared.b64 _, [%0], %1;" :: "r"(a), "r"(b) : "memory")
#define MBAR_ARRIVE(a) asm volatile("mbarrier.arrive.release.cta.shared.b64 _, [%0];" :: "r"(a) : "memory")
#define FENCE_ASYNC()  asm volatile("fence.proxy.async.shared::cta;" ::: "memory")
__device__ __forceinline__ void mbar_wait(uint32_t mbar, uint32_t parity) {
    asm volatile(
        "{\n\t.reg .pred P;\n\t"
        "WL_%=:\n\t"
        "mbarrier.try_wait.parity.acquire.cta.shared::cta.b64 P, [%0], %1, 0x989680;\n\t"
        "@!P bra WL_%=;\n\t}"
        :: "r"(mbar), "r"(parity) : "memory");
}
__device__ __forceinline__ void bulk_g2s(uint32_t dst, const void* src, uint32_t mbar) {
    asm volatile(
        "cp.async.bulk.shared::cluster.global.mbarrier::complete_tx::bytes "
        "[%0], [%1], %2, [%3];"
        :: "r"(dst), "l"(src), "r"((uint32_t)SUB_BYTES), "r"(mbar) : "memory");
}
__device__ __forceinline__ void ldsm4(uint32_t* r, uint32_t a) {
    asm volatile("ldmatrix.sync.aligned.m8n8.x4.shared.b16 {%0,%1,%2,%3}, [%4];"
                 : "=r"(r[0]), "=r"(r[1]), "=r"(r[2]), "=r"(r[3]) : "r"(a));
}
__device__ __forceinline__ void mma16816(float* d, const uint32_t* a,
                                         uint32_t b0, uint32_t b1) {
    asm volatile(
        "mma.sync.aligned.m16n8k16.row.col.f32.f16.f16.f32 "
        "{%0,%1,%2,%3}, {%4,%5,%6,%7}, {%8,%9}, {%0,%1,%2,%3};"
        : "+f"(d[0]), "+f"(d[1]), "+f"(d[2]), "+f"(d[3])
        : "r"(a[0]), "r"(a[1]), "r"(a[2]), "r"(a[3]), "r"(b0), "r"(b1));
}
__device__ __forceinline__ int ldcg_i(const int* p) {
    int v; asm volatile("ld.global.cg.s32 %0, [%1];" : "=r"(v) : "l"(p)); return v;
}
#define SWZ(x) ((x) ^ ((((uint32_t)(x)) >> 3) & 0x70))

// SMEM layout (relative to 1024-aligned base)
#define SM_FULL   0           // 4 x 8B mbarriers
#define SM_EMPTY  64          // 4 x 8B mbarriers
#define SM_FLAG   128
#define SM_XXI    256         // 128 float
#define SM_LABI   768         // 128 int
#define SM_XXJ    1280        // 128 float
#define SM_LABJ   1792        // 128 int
#define SM_STAGE  4096        // 4 stages x 32KB: A(16K) | B(16K)
#define STAGE_SZ  32768
#define SMEM_TOTAL (SM_STAGE + NSTG * STAGE_SZ + 1024)   // ~134KB -> 1 CTA/SM

// ---------------------------------------------------------------------------
// Prep: fp16 convert into chunk-major PRE-SWIZZLED layout, exact fp32 norms,
// label normalization, reduction + counter init. One warp per row.
// ---------------------------------------------------------------------------
__global__ void prep_kernel(const float* __restrict__ feat,
                            const int* __restrict__ lab_raw, int n) {
    int row  = blockIdx.x * 8 + (threadIdx.x >> 5);
    int lane = threadIdx.x & 31;
    if (row >= n) return;

    const float4* p = (const float4*)(feat + (size_t)row * DIMK);
    float4 v0 = p[2 * lane];
    float4 v1 = p[2 * lane + 1];

    float s = v0.x * v0.x + v0.y * v0.y + v0.z * v0.z + v0.w * v0.w
            + v1.x * v1.x + v1.y * v1.y + v1.z * v1.z + v1.w * v1.w;

    __half2 h0 = __floats2half2_rn(v0.x, v0.y);
    __half2 h1 = __floats2half2_rn(v0.z, v0.w);
    __half2 h2 = __floats2half2_rn(v1.x, v1.y);
    __half2 h3 = __floats2half2_rn(v1.z, v1.w);
    uint4 pk;
    pk.x = *(uint32_t*)&h0; pk.y = *(uint32_t*)&h1;
    pk.z = *(uint32_t*)&h2; pk.w = *(uint32_t*)&h3;

    const int blk = row >> 7;
    const int c   = lane >> 3;
    const uint32_t in_off = SWZ(((uint32_t)(row & 127)) * 128 + (lane & 7) * 16);
    char* dst = (char*)g_f16s + (((size_t)blk * NSC + c) << 14) + in_off;
    *(uint4*)dst = pk;

#pragma unroll
    for (int o = 16; o; o >>= 1) s += __shfl_xor_sync(0xffffffffu, s, o);

    if (lane == 0) {
        g_xx[row]     = s;
        g_posmax[row] = 0;
        g_negmin[row] = __float_as_int(FLT_MAX);
    }
    if (lane == 1) {
        bool is64 = true;
#pragma unroll
        for (int i = 0; i < 32; i++)
            if (lab_raw[2 * i + 1] != 0) { is64 = false; break; }
        g_lab[row] = is64 ? lab_raw[2 * row] : lab_raw[row];
    }
    if (row == 0 && lane == 2) g_done = 0;
}

// ---------------------------------------------------------------------------
__device__ __forceinline__ void decode_tile(int t, int ntb, int& bi, int& bj) {
    int ti = 0;
    while (t >= ntb - ti) { t -= ntb - ti; ti++; }
    bi = ti;
    bj = ti + t;
}

__device__ __forceinline__ void issue_chunk(uint32_t st, uint32_t fb,
                                            int ti, int tj, int c) {
    MBAR_EXPECT_TX(fb, 2 * SUB_BYTES);
    const char* A = (const char*)g_f16s + ((((size_t)ti) * NSC + c) << 14);
    const char* B = (const char*)g_f16s + ((((size_t)tj) * NSC + c) << 14);
    bulk_g2s(st,             A, fb);
    bulk_g2s(st + SUB_BYTES, B, fb);
}

// Load one k-step's operand fragments (2 a-LDSM + 2 b-LDSM).
__device__ __forceinline__ void ld_ops(uint32_t a[2][4], uint32_t b[2][4],
                                       uint32_t sA, uint32_t sB, int ks,
                                       uint32_t ra0, uint32_t rb0, uint32_t khi) {
    const uint32_t ko = (uint32_t)ks * 32 + khi;
    ldsm4(a[0], sA + SWZ(ra0 + ko));
    ldsm4(a[1], sA + SWZ(ra0 + 16 * 128 + ko));
    ldsm4(b[0], sB + SWZ(rb0 + ko));
    ldsm4(b[1], sB + SWZ(rb0 + 16 * 128 + ko));
}

// 8 HMMAs for one k-step (32x32 per warp), all-independent accumulators.
__device__ __forceinline__ void hmma8(float acc[2][4][4],
                                      uint32_t a[2][4], uint32_t b[2][4]) {
#pragma unroll
    for (int mt = 0; mt < 2; mt++)
#pragma unroll
        for (int nt = 0; nt < 4; nt++) {
            const int p = nt >> 1, q = nt & 1;
            mma16816(acc[mt][nt], a[mt], b[p][q], b[p][2 + q]);
        }
}

// ---------------------------------------------------------------------------
// Persistent kernel: 128x128 tiles, 16 warps of 32x32, 4-stage ring,
// SOFTWARE-PIPELINED operands (LDSM k+1 issued before HMMA k),
// fused final reduction.
// ---------------------------------------------------------------------------
__global__ void __launch_bounds__(NTHR, 1) tile_kernel(float* __restrict__ out, int n) {
    extern __shared__ char smem_raw[];
    uint32_t sb_raw = s2u(smem_raw);
    uint32_t pad = (1024u - (sb_raw & 1023u)) & 1023u;
    char* sm = smem_raw + pad;
    uint32_t sb = sb_raw + pad;

    float* xxi_s  = (float*)(sm + SM_XXI);
    int*   labi_s = (int*)(sm + SM_LABI);
    float* xxj_s  = (float*)(sm + SM_XXJ);
    int*   labj_s = (int*)(sm + SM_LABJ);

    const int tid = threadIdx.x, lane = tid & 31, w = tid >> 5;
    const int m_base = (w & 3) * 32;     // 4 warps along M
    const int n_base = (w >> 2) * 32;    // 4 warps along N
    const uint32_t ra0 = (uint32_t)(m_base + (lane & 15)) * 128;
    const uint32_t rb0 = (uint32_t)(n_base + (lane & 15)) * 128;
    const uint32_t khi = (uint32_t)((lane >> 4) << 4);

    const int ntb = n >> 7;
    const int T   = ntb * (ntb + 1) / 2;          // 528 triangle tiles
    const int myT = (T - (int)blockIdx.x + (int)gridDim.x - 1) / (int)gridDim.x;
    const int G   = myT * NCH;

    if (tid == 0) {
#pragma unroll
        for (int s = 0; s < NSTG; s++) {
            MBAR_INIT(sb + SM_FULL + s * 8, 1);
            MBAR_INIT(sb + SM_EMPTY + s * 8, 16);
        }
    }
    __syncthreads();

    if (G > 0) {
        int ti, tj;
        decode_tile(blockIdx.x, ntb, ti, tj);
        if (tid == 0) {
#pragma unroll
            for (int c = 0; c < NSTG; c++)
                if (c < G)
                    issue_chunk(sb + SM_STAGE + c * STAGE_SZ,
                                sb + SM_FULL + c * 8, ti, tj, c);
        }
        // stage tile 0 epilogue operands
        if (tid < 128) {
            xxi_s[tid]  = g_xx[ti * 128 + tid];
            labi_s[tid] = g_lab[ti * 128 + tid];
        } else if (tid < 256) {
            int q = tid - 128;
            xxj_s[q]  = g_xx[tj * 128 + q];
            labj_s[q] = g_lab[tj * 128 + q];
        }
        __syncthreads();

        float acc[2][4][4];
        uint32_t A0[2][4], B0[2][4], A1[2][4], B1[2][4];
#pragma unroll
        for (int a = 0; a < 2; a++)
#pragma unroll
            for (int b = 0; b < 4; b++)
#pragma unroll
                for (int e = 0; e < 4; e++) acc[a][b][e] = 0.f;

        // prologue: chunk 0, k-step 0 operands
        mbar_wait(sb + SM_FULL, 0);
        {
            uint32_t sA = sb + SM_STAGE, sB = sA + SUB_BYTES;
            ld_ops(A0, B0, sA, sB, 0, ra0, rb0, khi);
        }

        for (int g = 0; g < G; g++) {
            const int s = g & 3;                  // stage == chunk-in-tile
            const uint32_t sA = sb + SM_STAGE + s * STAGE_SZ;
            const uint32_t sB = sA + SUB_BYTES;

            // pipelined k-steps: prefetch next ops, then HMMA current
            ld_ops(A1, B1, sA, sB, 1, ra0, rb0, khi);
            hmma8(acc, A0, B0);
            ld_ops(A0, B0, sA, sB, 2, ra0, rb0, khi);
            hmma8(acc, A1, B1);
            ld_ops(A1, B1, sA, sB, 3, ra0, rb0, khi);
            hmma8(acc, A0, B0);
            hmma8(acc, A1, B1);                   // k-step 3 (no prefetch target yet)

            if (lane == 0) MBAR_ARRIVE(sb + SM_EMPTY + s * 8);

            // prefetch next chunk's k-step 0 (covered by epilogue when present)
            if (g + 1 < G) {
                mbar_wait(sb + SM_FULL + ((g + 1) & 3) * 8,
                          (uint32_t)(((g + 1) >> 2) & 1));
                uint32_t nA = sb + SM_STAGE + ((g + 1) & 3) * STAGE_SZ;
                ld_ops(A0, B0, nA, nA + SUB_BYTES, 0, ra0, rb0, khi);
            }

            // producer: refill stage s with chunk g+4 (needs empty(g))
            if (tid == 0 && g + NSTG < G) {
                mbar_wait(sb + SM_EMPTY + s * 8, (uint32_t)((g >> 2) & 1));
                FENCE_ASYNC();
                int lti, ltj;
                decode_tile((int)blockIdx.x + (((g + NSTG) >> 2)) * (int)gridDim.x,
                            ntb, lti, ltj);
                issue_chunk(sb + SM_STAGE + s * STAGE_SZ,
                            sb + SM_FULL + s * 8, lti, ltj, (g + NSTG) & 3);
            }

            if (s == 3) {
                // ---- epilogue over this warp's 32x32 block ----
                float xi[4]; int li[4];
#pragma unroll
                for (int mt = 0; mt < 2; mt++)
#pragma unroll
                    for (int rh = 0; rh < 2; rh++) {
                        int r = m_base + mt * 16 + (lane >> 2) + 8 * rh;
                        xi[mt * 2 + rh] = xxi_s[r];
                        li[mt * 2 + rh] = labi_s[r];
                    }
                float xj[8]; int lj[8];
#pragma unroll
                for (int nt = 0; nt < 4; nt++)
#pragma unroll
                    for (int cc = 0; cc < 2; cc++) {
                        int q = n_base + nt * 8 + (lane & 3) * 2 + cc;
                        xj[nt * 2 + cc] = xxj_s[q];
                        lj[nt * 2 + cc] = labj_s[q];
                    }
#pragma unroll
                for (int mt = 0; mt < 2; mt++)
#pragma unroll
                    for (int nt = 0; nt < 4; nt++)
#pragma unroll
                        for (int e = 0; e < 4; e++) {
                            int rh = e >> 1, cc = e & 1;
                            acc[mt][nt][e] = fmaf(-2.f, acc[mt][nt][e],
                                                  xi[mt * 2 + rh] + xj[nt * 2 + cc]);
                        }

                // row direction
#pragma unroll
                for (int mt = 0; mt < 2; mt++)
#pragma unroll
                    for (int rh = 0; rh < 2; rh++) {
                        float pm = -1.f, nm = FLT_MAX;
                        const int L = li[mt * 2 + rh];
#pragma unroll
                        for (int nt = 0; nt < 4; nt++)
#pragma unroll
                            for (int cc = 0; cc < 2; cc++) {
                                float v = acc[mt][nt][rh * 2 + cc];
                                if (L == lj[nt * 2 + cc]) pm = fmaxf(pm, v);
                                else                      nm = fminf(nm, v);
                            }
                        pm = fmaxf(pm, __shfl_xor_sync(0xffffffffu, pm, 1));
                        pm = fmaxf(pm, __shfl_xor_sync(0xffffffffu, pm, 2));
                        nm = fminf(nm, __shfl_xor_sync(0xffffffffu, nm, 1));
                        nm = fminf(nm, __shfl_xor_sync(0xffffffffu, nm, 2));
                        if ((lane & 3) == 0) {
                            int gi = ti * 128 + m_base + mt * 16 + (lane >> 2) + 8 * rh;
                            atomicMax(&g_posmax[gi], __float_as_int(pm));
                            atomicMin(&g_negmin[gi], __float_as_int(nm));
                        }
                    }

                // column direction (symmetry)
#pragma unroll
                for (int nt = 0; nt < 4; nt++)
#pragma unroll
                    for (int cc = 0; cc < 2; cc++) {
                        float pm = -1.f, nm = FLT_MAX;
                        const int L = lj[nt * 2 + cc];
#pragma unroll
                        for (int mt = 0; mt < 2; mt++)
#pragma unroll
                            for (int rh = 0; rh < 2; rh++) {
                                float v = acc[mt][nt][rh * 2 + cc];
                                if (L == li[mt * 2 + rh]) pm = fmaxf(pm, v);
                                else                      nm = fminf(nm, v);
                            }
                        pm = fmaxf(pm, __shfl_xor_sync(0xffffffffu, pm, 4));
                        pm = fmaxf(pm, __shfl_xor_sync(0xffffffffu, pm, 8));
                        pm = fmaxf(pm, __shfl_xor_sync(0xffffffffu, pm, 16));
                        nm = fminf(nm, __shfl_xor_sync(0xffffffffu, nm, 4));
                        nm = fminf(nm, __shfl_xor_sync(0xffffffffu, nm, 8));
                        nm = fminf(nm, __shfl_xor_sync(0xffffffffu, nm, 16));
                        if (lane < 4) {
                            int gj = tj * 128 + n_base + nt * 8 + (lane & 3) * 2 + cc;
                            atomicMax(&g_posmax[gj], __float_as_int(pm));
                            atomicMin(&g_negmin[gj], __float_as_int(nm));
                        }
                    }

                if (g + 1 < G) {
                    decode_tile((int)blockIdx.x + ((g >> 2) + 1) * (int)gridDim.x,
                                ntb, ti, tj);
                    __syncthreads();              // all warps done with xx/lab
                    if (tid < 128) {
                        xxi_s[tid]  = g_xx[ti * 128 + tid];
                        labi_s[tid] = g_lab[ti * 128 + tid];
                    } else if (tid < 256) {
                        int q = tid - 128;
                        xxj_s[q]  = g_xx[tj * 128 + q];
                        labj_s[q] = g_lab[tj * 128 + q];
                    }
                    __syncthreads();
#pragma unroll
                    for (int a = 0; a < 2; a++)
#pragma unroll
                        for (int b = 0; b < 4; b++)
#pragma unroll
                            for (int e = 0; e < 4; e++) acc[a][b][e] = 0.f;
                }
            }
        }
    }

    // ---- completion counter: last CTA performs the finalize reduction ----
    __syncthreads();
    if (tid == 0) {
        __threadfence();
        int prev = atomicAdd(&g_done, 1);
        *(volatile int*)(sm + SM_FLAG) = (prev == (int)gridDim.x - 1) ? 1 : 0;
    }
    __syncthreads();
    if (*(volatile int*)(sm + SM_FLAG)) {
        float* ss = (float*)(sm + SM_STAGE);
        float* sc = ss + NTHR;
        float sum = 0.f, cnt = 0.f;
        for (int i = tid; i < n; i += NTHR) {
            float ap2 = __int_as_float(ldcg_i(&g_posmax[i]));
            float ap  = sqrtf(fmaxf(ap2, 1e-12f));
            float nm2 = __int_as_float(ldcg_i(&g_negmin[i]));
            bool  has_neg = nm2 < 1e30f;
            float an  = has_neg ? sqrtf(fmaxf(nm2, 1e-12f)) : 0.f;
            bool  valid = (ap < 1000000.0f) && (an > 0.f);
            if (valid) {
                sum += fmaxf(0.3f + ap - an, 0.f);
                cnt += 1.f;
            }
        }
        ss[tid] = sum;
        sc[tid] = cnt;
        __syncthreads();
        for (int o = NTHR / 2; o; o >>= 1) {
            if (tid < o) {
                ss[tid] += ss[tid + o];
                sc[tid] += sc[tid + o];
            }
            __syncthreads();
        }
        if (tid == 0)
            out[0] = (sc[0] > 0.f) ? ss[0] / fmaxf(sc[0], 1.f) : 0.f;
    }
}

// ---------------------------------------------------------------------------
extern "C" void kernel_launch(void* const* d_in, const int* in_sizes, int n_in,
                              void* d_out, int out_size) {
    const float* feat   = (const float*)d_in[0];
    const int*   labels = (const int*)d_in[1];   // int32/int64 auto-detected
    int n = in_sizes[1];                         // 4096

    cudaFuncSetAttribute(tile_kernel, cudaFuncAttributeMaxDynamicSharedMemorySize,
                         SMEM_TOTAL);

    prep_kernel<<<(n + 7) / 8, 256>>>(feat, labels, n);
    tile_kernel<<<148, NTHR, SMEM_TOTAL>>>((float*)d_out, n);
}

// round 13
// speedup vs baseline: 1.1243x; 1.1243x over previous
#include <cuda_runtime.h>
#include <cuda_fp16.h>
#include <float.h>
#include <stdint.h>

#define NMAX 4096
#define DIMK 256              // fp32 features per row
#define NSC  4                // 16KB sub-chunks per 128-row block (64 cols each)
#define NSTG 2                // smem pipeline stages
#define NTHR 512
#define SUB_BYTES   16384
#define BLOCK_BYTES 32768     // 128 rows x 128 kcols (2 contiguous sub-chunks)

// ---------------- device scratch (no allocs allowed) ----------------
__device__ int   g_posmax[NMAX];
__device__ int   g_negmin[NMAX];
__device__ float g_xx[NMAX];
__device__ int   g_lab[NMAX];
__device__ int   g_bar;                          // prep grid-barrier counter
__device__ int   g_done;                         // finalize election counter
// chunk-major pre-swizzled fp16 features:
// block b = row/128, sub-chunk c = col/64 -> contiguous 16KB at ((b*4+c)<<14)
__device__ __align__(16) __half g_f16s[NMAX * DIMK];

// ---------------- PTX helpers (sm_90-baseline ISA) ----------------
__device__ __forceinline__ uint32_t s2u(const void* p) {
    uint32_t a;
    asm("{ .reg .u64 t; cvta.to.shared.u64 t, %1; cvt.u32.u64 %0, t; }" : "=r"(a) : "l"(p));
    return a;
}
#define MBAR_INIT(a, c) asm volatile("mbarrier.init.shared.b64 [%0], %1;" :: "r"(a), "r"(c) : "memory")
#define MBAR_EXPECT_TX(a, b) asm volatile("mbarrier.arrive.expect_tx.shared.b64 _, [%0], %1;" :: "r"(a), "r"(b) : "memory")
#define MBAR_ARRIVE(a) asm volatile("mbarrier.arrive.release.cta.shared.b64 _, [%0];" :: "r"(a) : "memory")
#define FENCE_ASYNC()  asm volatile("fence.proxy.async.shared::cta;" ::: "memory")
__device__ __forceinline__ void mbar_wait(uint32_t mbar, uint32_t parity) {
    asm volatile(
        "{\n\t.reg .pred P;\n\t"
        "WL_%=:\n\t"
        "mbarrier.try_wait.parity.acquire.cta.shared::cta.b64 P, [%0], %1, 0x989680;\n\t"
        "@!P bra WL_%=;\n\t}"
        :: "r"(mbar), "r"(parity) : "memory");
}
__device__ __forceinline__ void bulk_g2s(uint32_t dst, const void* src, uint32_t mbar) {
    asm volatile(
        "cp.async.bulk.shared::cluster.global.mbarrier::complete_tx::bytes "
        "[%0], [%1], %2, [%3];"
        :: "r"(dst), "l"(src), "r"((uint32_t)BLOCK_BYTES), "r"(mbar) : "memory");
}
__device__ __forceinline__ void ldsm4(uint32_t* r, uint32_t a) {
    asm volatile("ldmatrix.sync.aligned.m8n8.x4.shared.b16 {%0,%1,%2,%3}, [%4];"
                 : "=r"(r[0]), "=r"(r[1]), "=r"(r[2]), "=r"(r[3]) : "r"(a));
}
__device__ __forceinline__ void mma16816(float* d, const uint32_t* a,
                                         uint32_t b0, uint32_t b1) {
    asm volatile(
        "mma.sync.aligned.m16n8k16.row.col.f32.f16.f16.f32 "
        "{%0,%1,%2,%3}, {%4,%5,%6,%7}, {%8,%9}, {%0,%1,%2,%3};"
        : "+f"(d[0]), "+f"(d[1]), "+f"(d[2]), "+f"(d[3])
        : "r"(a[0]), "r"(a[1]), "r"(a[2]), "r"(a[3]), "r"(b0), "r"(b1));
}
__device__ __forceinline__ int ldcg_i(const int* p) {
    int v; asm volatile("ld.global.cg.s32 %0, [%1];" : "=r"(v) : "l"(p)); return v;
}
#define SWZ(x) ((x) ^ ((((uint32_t)(x)) >> 3) & 0x70))

// SMEM layout (relative to 1024-aligned base)
#define SM_FULL   0           // 2 x 8B mbarriers
#define SM_EMPTY  64          // 2 x 8B mbarriers
#define SM_FLAG   128
#define SM_XXI    256         // 128 float
#define SM_LABI   768         // 128 int
#define SM_XXJ    1280        // 256 float
#define SM_LABJ   2304        // 256 int
#define SM_STAGE  4096        // 2 stages x 96KB: A(32K) | B0(32K) | B1(32K)
#define STAGE_SZ  98304
#define SMEM_TOTAL (SM_STAGE + NSTG * STAGE_SZ + 1024)   // ~198KB -> 1 CTA/SM

// ---------------------------------------------------------------------------
// Supertile enumeration: (ti, sj) with j-superblock sj covering blocks
// {2sj, 2sj+1}, kept if 2sj+1 >= ti. Duplicate transpose halves are harmless
// (max/min idempotent). Count = 272 for ntb=32.
// ---------------------------------------------------------------------------
__device__ __forceinline__ void decode_st(int t, int nsb, int& ti, int& sj) {
    ti = 0;
    while (t >= nsb - (ti >> 1)) { t -= nsb - (ti >> 1); ti++; }
    sj = (ti >> 1) + t;
}

// Refill one big-chunk (128 kcols): A + B0 + B1, three 32KB bulk copies.
__device__ __forceinline__ void issue_bigchunk(uint32_t st, uint32_t fb,
                                               int ti, int sj, int c2) {
    MBAR_EXPECT_TX(fb, 3 * BLOCK_BYTES);
    const char* A  = (const char*)g_f16s + ((((size_t)ti)           * NSC + c2 * 2) << 14);
    const char* B0 = (const char*)g_f16s + ((((size_t)(2 * sj))     * NSC + c2 * 2) << 14);
    const char* B1 = (const char*)g_f16s + ((((size_t)(2 * sj + 1)) * NSC + c2 * 2) << 14);
    bulk_g2s(st,                   A,  fb);
    bulk_g2s(st + BLOCK_BYTES,     B0, fb);
    bulk_g2s(st + 2 * BLOCK_BYTES, B1, fb);
}

// MMA over one 128-kcol big-chunk, per-warp 32x64 output.
__device__ __forceinline__ void mma_bigchunk(float acc[2][8][4], uint32_t st,
                                             int m_base, int n_base, int lane) {
    const uint32_t sA = st;
    const uint32_t sB = st + BLOCK_BYTES + ((uint32_t)(n_base >> 7)) * BLOCK_BYTES;
    const int nloc = n_base & 64;
#pragma unroll
    for (int s8 = 0; s8 < 8; s8++) {
        const int sc = s8 >> 2, ks = s8 & 3;
        const uint32_t so = (uint32_t)sc * SUB_BYTES;
        const uint32_t koff = (uint32_t)ks * 32 + ((lane >> 4) << 4);
        uint32_t a[2][4], b[4][4];
#pragma unroll
        for (int mt = 0; mt < 2; mt++) {
            uint32_t ad = SWZ((uint32_t)(m_base + mt * 16 + (lane & 15)) * 128 + koff);
            ldsm4(a[mt], sA + so + ad);
        }
#pragma unroll
        for (int p = 0; p < 4; p++) {
            uint32_t bd = SWZ((uint32_t)(nloc + p * 16 + (lane & 15)) * 128 + koff);
            ldsm4(b[p], sB + so + bd);
        }
#pragma unroll
        for (int mt = 0; mt < 2; mt++)
#pragma unroll
            for (int nt = 0; nt < 8; nt++) {
                const int p = nt >> 1, q = nt & 1;
                mma16816(acc[mt][nt], a[mt], b[p][q], b[p][2 + q]);
            }
    }
}

// ---------------------------------------------------------------------------
// ONE fused persistent kernel:
//   phase 1: prep (fp16 swizzled convert, norms, labels, init)
//   grid barrier (all 148 CTAs resident: 1 CTA/SM guaranteed by smem)
//   phase 2: 128x256 supertiles, 2-stage 96KB ring, early producer
//   phase 3: last CTA reduces the loss + resets counters for graph replay
// ---------------------------------------------------------------------------
__global__ void __launch_bounds__(NTHR, 1)
fused_kernel(float* __restrict__ out,
             const float* __restrict__ feat,
             const int* __restrict__ lab_raw, int n) {
    extern __shared__ char smem_raw[];
    uint32_t sb_raw = s2u(smem_raw);
    uint32_t pad = (1024u - (sb_raw & 1023u)) & 1023u;
    char* sm = smem_raw + pad;
    uint32_t sb = sb_raw + pad;

    float* xxi_s  = (float*)(sm + SM_XXI);
    int*   labi_s = (int*)(sm + SM_LABI);
    float* xxj_s  = (float*)(sm + SM_XXJ);
    int*   labj_s = (int*)(sm + SM_LABJ);

    const int tid = threadIdx.x, lane = tid & 31, w = tid >> 5;

    // ================= phase 1: prep (one warp per row, grid-strided) =======
    const int warps_total = (int)gridDim.x * (NTHR / 32);
    for (int row = (int)blockIdx.x * (NTHR / 32) + w; row < n; row += warps_total) {
        const float4* p = (const float4*)(feat + (size_t)row * DIMK);
        float4 v0 = p[2 * lane];
        float4 v1 = p[2 * lane + 1];

        float s = v0.x * v0.x + v0.y * v0.y + v0.z * v0.z + v0.w * v0.w
                + v1.x * v1.x + v1.y * v1.y + v1.z * v1.z + v1.w * v1.w;

        __half2 h0 = __floats2half2_rn(v0.x, v0.y);
        __half2 h1 = __floats2half2_rn(v0.z, v0.w);
        __half2 h2 = __floats2half2_rn(v1.x, v1.y);
        __half2 h3 = __floats2half2_rn(v1.z, v1.w);
        uint4 pk;
        pk.x = *(uint32_t*)&h0; pk.y = *(uint32_t*)&h1;
        pk.z = *(uint32_t*)&h2; pk.w = *(uint32_t*)&h3;

        const int blk = row >> 7;
        const int c   = lane >> 3;
        const uint32_t in_off = SWZ(((uint32_t)(row & 127)) * 128 + (lane & 7) * 16);
        char* dst = (char*)g_f16s + (((size_t)blk * NSC + c) << 14) + in_off;
        *(uint4*)dst = pk;

#pragma unroll
        for (int o = 16; o; o >>= 1) s += __shfl_xor_sync(0xffffffffu, s, o);

        if (lane == 0) {
            g_xx[row]     = s;
            g_posmax[row] = 0;
            g_negmin[row] = __float_as_int(FLT_MAX);
        }
        if (lane == 1) {
            bool is64 = true;
#pragma unroll
            for (int i = 0; i < 32; i++)
                if (lab_raw[2 * i + 1] != 0) { is64 = false; break; }
            g_lab[row] = is64 ? lab_raw[2 * row] : lab_raw[row];
        }
    }

    // mbarrier init (before the grid barrier so it's ready immediately after)
    if (tid == 0) {
#pragma unroll
        for (int s = 0; s < NSTG; s++) {
            MBAR_INIT(sb + SM_FULL + s * 8, 1);
            MBAR_INIT(sb + SM_EMPTY + s * 8, 16);
        }
    }

    // ================= grid barrier (all CTAs resident -> no deadlock) ======
    __syncthreads();
    if (tid == 0) {
        __threadfence();
        atomicAdd(&g_bar, 1);
        while (ldcg_i(&g_bar) < (int)gridDim.x) { }
        __threadfence();
    }
    __syncthreads();

    // ================= phase 2: supertile GEMM + masked reductions ==========
    const int m_base = (w & 3) * 32;     // 4 warps along M (128 rows)
    const int n_base = (w >> 2) * 64;    // 4 warps along N (256 cols)

    const int ntb = n >> 7;
    const int nsb = ntb >> 1;
    int ST = 0;
    for (int t2 = 0; t2 < ntb; t2++) ST += nsb - (t2 >> 1);
    const int myST = (ST - (int)blockIdx.x + (int)gridDim.x - 1) / (int)gridDim.x;
    const int G    = myST * 2;

    if (G > 0) {
        int ti0, sj0;
        decode_st(blockIdx.x, nsb, ti0, sj0);
        if (tid == 0) {
            issue_bigchunk(sb + SM_STAGE,            sb + SM_FULL,     ti0, sj0, 0);
            issue_bigchunk(sb + SM_STAGE + STAGE_SZ, sb + SM_FULL + 8, ti0, sj0, 1);
        }

        float acc[2][8][4];
        int ti = ti0, sj = sj0;

        for (int g = 0; g < G; g++) {
            const int s = g & 1;

            if ((g & 1) == 0) {
                if (g > 0) decode_st((int)blockIdx.x + (g >> 1) * (int)gridDim.x,
                                     nsb, ti, sj);
                __syncthreads();                   // prev epilogue done reading
                if (tid < 128) {
                    xxi_s[tid]  = g_xx[ti * 128 + tid];
                    labi_s[tid] = g_lab[ti * 128 + tid];
                } else if (tid < 384) {
                    int q = tid - 128;
                    xxj_s[q]  = g_xx[sj * 256 + q];
                    labj_s[q] = g_lab[sj * 256 + q];
                }
                __syncthreads();
#pragma unroll
                for (int a = 0; a < 2; a++)
#pragma unroll
                    for (int b = 0; b < 8; b++)
#pragma unroll
                        for (int e = 0; e < 4; e++) acc[a][b][e] = 0.f;
            }

            // early producer: refill the OTHER stage (released at chunk g-1)
            if (tid == 0 && g >= 1 && g + 1 < G) {
                uint32_t ep = (uint32_t)((((g + 1) >> 1) - 1) & 1);
                mbar_wait(sb + SM_EMPTY + (s ^ 1) * 8, ep);
                FENCE_ASYNC();
                int lti, lsj;
                decode_st((int)blockIdx.x + ((g + 1) >> 1) * (int)gridDim.x,
                          nsb, lti, lsj);
                issue_bigchunk(sb + SM_STAGE + (s ^ 1) * STAGE_SZ,
                               sb + SM_FULL + (s ^ 1) * 8, lti, lsj, (g + 1) & 1);
            }

            mbar_wait(sb + SM_FULL + s * 8, (uint32_t)((g >> 1) & 1));
            mma_bigchunk(acc, sb + SM_STAGE + s * STAGE_SZ, m_base, n_base, lane);
            if (lane == 0) MBAR_ARRIVE(sb + SM_EMPTY + s * 8);

            if ((g & 1) == 1) {
                // ---- epilogue over this warp's 32x64 block ----
                float xi[4]; int li[4];
#pragma unroll
                for (int mt = 0; mt < 2; mt++)
#pragma unroll
                    for (int rh = 0; rh < 2; rh++) {
                        int r = m_base + mt * 16 + (lane >> 2) + 8 * rh;
                        xi[mt * 2 + rh] = xxi_s[r];
                        li[mt * 2 + rh] = labi_s[r];
                    }
                float xj[16]; int lj[16];
#pragma unroll
                for (int nt = 0; nt < 8; nt++)
#pragma unroll
                    for (int cc = 0; cc < 2; cc++) {
                        int q = n_base + nt * 8 + (lane & 3) * 2 + cc;
                        xj[nt * 2 + cc] = xxj_s[q];
                        lj[nt * 2 + cc] = labj_s[q];
                    }
#pragma unroll
                for (int mt = 0; mt < 2; mt++)
#pragma unroll
                    for (int nt = 0; nt < 8; nt++)
#pragma unroll
                        for (int e = 0; e < 4; e++) {
                            int rh = e >> 1, cc = e & 1;
                            acc[mt][nt][e] = fmaf(-2.f, acc[mt][nt][e],
                                                  xi[mt * 2 + rh] + xj[nt * 2 + cc]);
                        }

                // row direction
#pragma unroll
                for (int mt = 0; mt < 2; mt++)
#pragma unroll
                    for (int rh = 0; rh < 2; rh++) {
                        float pm = -1.f, nm = FLT_MAX;
                        const int L = li[mt * 2 + rh];
#pragma unroll
                        for (int nt = 0; nt < 8; nt++)
#pragma unroll
                            for (int cc = 0; cc < 2; cc++) {
                                float v = acc[mt][nt][rh * 2 + cc];
                                if (L == lj[nt * 2 + cc]) pm = fmaxf(pm, v);
                                else                      nm = fminf(nm, v);
                            }
                        pm = fmaxf(pm, __shfl_xor_sync(0xffffffffu, pm, 1));
                        pm = fmaxf(pm, __shfl_xor_sync(0xffffffffu, pm, 2));
                        nm = fminf(nm, __shfl_xor_sync(0xffffffffu, nm, 1));
                        nm = fminf(nm, __shfl_xor_sync(0xffffffffu, nm, 2));
                        if ((lane & 3) == 0) {
                            int gi = ti * 128 + m_base + mt * 16 + (lane >> 2) + 8 * rh;
                            atomicMax(&g_posmax[gi], __float_as_int(pm));
                            atomicMin(&g_negmin[gi], __float_as_int(nm));
                        }
                    }

                // column direction (symmetry)
#pragma unroll
                for (int nt = 0; nt < 8; nt++)
#pragma unroll
                    for (int cc = 0; cc < 2; cc++) {
                        float pm = -1.f, nm = FLT_MAX;
                        const int L = lj[nt * 2 + cc];
#pragma unroll
                        for (int mt = 0; mt < 2; mt++)
#pragma unroll
                            for (int rh = 0; rh < 2; rh++) {
                                float v = acc[mt][nt][rh * 2 + cc];
                                if (L == li[mt * 2 + rh]) pm = fmaxf(pm, v);
                                else                      nm = fminf(nm, v);
                            }
                        pm = fmaxf(pm, __shfl_xor_sync(0xffffffffu, pm, 4));
                        pm = fmaxf(pm, __shfl_xor_sync(0xffffffffu, pm, 8));
                        pm = fmaxf(pm, __shfl_xor_sync(0xffffffffu, pm, 16));
                        nm = fminf(nm, __shfl_xor_sync(0xffffffffu, nm, 4));
                        nm = fminf(nm, __shfl_xor_sync(0xffffffffu, nm, 8));
                        nm = fminf(nm, __shfl_xor_sync(0xffffffffu, nm, 16));
                        if (lane < 4) {
                            int gj = sj * 256 + n_base + nt * 8 + (lane & 3) * 2 + cc;
                            atomicMax(&g_posmax[gj], __float_as_int(pm));
                            atomicMin(&g_negmin[gj], __float_as_int(nm));
                        }
                    }
            }
        }
    }

    // ================= phase 3: last CTA reduces loss, resets counters ======
    __syncthreads();
    if (tid == 0) {
        __threadfence();
        int prev = atomicAdd(&g_done, 1);
        *(volatile int*)(sm + SM_FLAG) = (prev == (int)gridDim.x - 1) ? 1 : 0;
    }
    __syncthreads();
    if (*(volatile int*)(sm + SM_FLAG)) {
        float* ss = (float*)(sm + SM_STAGE);
        float* sc = ss + NTHR;
        float sum = 0.f, cnt = 0.f;
        for (int i = tid; i < n; i += NTHR) {
            float ap2 = __int_as_float(ldcg_i(&g_posmax[i]));
            float ap  = sqrtf(fmaxf(ap2, 1e-12f));
            float nm2 = __int_as_float(ldcg_i(&g_negmin[i]));
            bool  has_neg = nm2 < 1e30f;
            float an  = has_neg ? sqrtf(fmaxf(nm2, 1e-12f)) : 0.f;
            bool  valid = (ap < 1000000.0f) && (an > 0.f);
            if (valid) {
                sum += fmaxf(0.3f + ap - an, 0.f);
                cnt += 1.f;
            }
        }
        ss[tid] = sum;
        sc[tid] = cnt;
        __syncthreads();
        for (int o = NTHR / 2; o; o >>= 1) {
            if (tid < o) {
                ss[tid] += ss[tid + o];
                sc[tid] += sc[tid + o];
            }
            __syncthreads();
        }
        if (tid == 0) {
            out[0] = (sc[0] > 0.f) ? ss[0] / fmaxf(sc[0], 1.f) : 0.f;
            g_bar  = 0;                            // reset for next graph replay
            g_done = 0;
        }
    }
}

// ---------------------------------------------------------------------------
extern "C" void kernel_launch(void* const* d_in, const int* in_sizes, int n_in,
                              void* d_out, int out_size) {
    const float* feat   = (const float*)d_in[0];
    const int*   labels = (const int*)d_in[1];   // int32/int64 auto-detected
    int n = in_sizes[1];                         // 4096

    cudaFuncSetAttribute(fused_kernel, cudaFuncAttributeMaxDynamicSharedMemorySize,
                         SMEM_TOTAL);

    fused_kernel<<<148, NTHR, SMEM_TOTAL>>>((float*)d_out, feat, labels, n);
}

// round 14
// speedup vs baseline: 1.1623x; 1.0338x over previous
#include <cuda_runtime.h>
#include <cuda_fp16.h>
#include <float.h>
#include <stdint.h>

#define NMAX 4096
#define DIMK 256              // fp32 features per row
#define NSC  4                // 16KB sub-chunks per 128-row block (64 cols each)
#define NSTG 2                // smem pipeline stages
#define NTHR 1024             // 32 warps -> 8 per SMSP (latency hiding)
#define SUB_BYTES   16384
#define BLOCK_BYTES 32768     // 128 rows x 128 kcols (2 contiguous sub-chunks)

// ---------------- device scratch (no allocs allowed) ----------------
__device__ int   g_posmax[NMAX];
__device__ int   g_negmin[NMAX];
__device__ float g_xx[NMAX];
__device__ int   g_lab[NMAX];
__device__ int   g_done;
// chunk-major pre-swizzled fp16 features:
// block b = row/128, sub-chunk c = col/64 -> contiguous 16KB at ((b*4+c)<<14)
__device__ __align__(16) __half g_f16s[NMAX * DIMK];

// ---------------- PTX helpers (sm_90-baseline ISA) ----------------
__device__ __forceinline__ uint32_t s2u(const void* p) {
    uint32_t a;
    asm("{ .reg .u64 t; cvta.to.shared.u64 t, %1; cvt.u32.u64 %0, t; }" : "=r"(a) : "l"(p));
    return a;
}
#define MBAR_INIT(a, c) asm volatile("mbarrier.init.shared.b64 [%0], %1;" :: "r"(a), "r"(c) : "memory")
#define MBAR_EXPECT_TX(a, b) asm volatile("mbarrier.arrive.expect_tx.shared.b64 _, [%0], %1;" :: "r"(a), "r"(b) : "memory")
#define MBAR_ARRIVE(a) asm volatile("mbarrier.arrive.release.cta.shared.b64 _, [%0];" :: "r"(a) : "memory")
#define FENCE_ASYNC()  asm volatile("fence.proxy.async.shared::cta;" ::: "memory")
__device__ __forceinline__ void mbar_wait(uint32_t mbar, uint32_t parity) {
    asm volatile(
        "{\n\t.reg .pred P;\n\t"
        "WL_%=:\n\t"
        "mbarrier.try_wait.parity.acquire.cta.shared::cta.b64 P, [%0], %1, 0x989680;\n\t"
        "@!P bra WL_%=;\n\t}"
        :: "r"(mbar), "r"(parity) : "memory");
}
__device__ __forceinline__ void bulk_g2s(uint32_t dst, const void* src, uint32_t mbar) {
    asm volatile(
        "cp.async.bulk.shared::cluster.global.mbarrier::complete_tx::bytes "
        "[%0], [%1], %2, [%3];"
        :: "r"(dst), "l"(src), "r"((uint32_t)BLOCK_BYTES), "r"(mbar) : "memory");
}
__device__ __forceinline__ void ldsm4(uint32_t* r, uint32_t a) {
    asm volatile("ldmatrix.sync.aligned.m8n8.x4.shared.b16 {%0,%1,%2,%3}, [%4];"
                 : "=r"(r[0]), "=r"(r[1]), "=r"(r[2]), "=r"(r[3]) : "r"(a));
}
__device__ __forceinline__ void mma16816(float* d, const uint32_t* a,
                                         uint32_t b0, uint32_t b1) {
    asm volatile(
        "mma.sync.aligned.m16n8k16.row.col.f32.f16.f16.f32 "
        "{%0,%1,%2,%3}, {%4,%5,%6,%7}, {%8,%9}, {%0,%1,%2,%3};"
        : "+f"(d[0]), "+f"(d[1]), "+f"(d[2]), "+f"(d[3])
        : "r"(a[0]), "r"(a[1]), "r"(a[2]), "r"(a[3]), "r"(b0), "r"(b1));
}
__device__ __forceinline__ int ldcg_i(const int* p) {
    int v; asm volatile("ld.global.cg.s32 %0, [%1];" : "=r"(v) : "l"(p)); return v;
}
#define SWZ(x) ((x) ^ ((((uint32_t)(x)) >> 3) & 0x70))

// SMEM layout (relative to 1024-aligned base)
#define SM_FULL   0           // 2 x 8B mbarriers
#define SM_EMPTY  64          // 2 x 8B mbarriers
#define SM_FLAG   128
#define SM_XXI    256         // 128 float
#define SM_LABI   768         // 128 int
#define SM_XXJ    1280        // 256 float
#define SM_LABJ   2304        // 256 int
#define SM_STAGE  4096        // 2 stages x 96KB: A(32K) | B0(32K) | B1(32K)
#define STAGE_SZ  98304
#define SMEM_TOTAL (SM_STAGE + NSTG * STAGE_SZ + 1024)   // ~198KB -> 1 CTA/SM

// ---------------------------------------------------------------------------
// Prep: fp16 convert into chunk-major PRE-SWIZZLED layout, exact fp32 norms,
// label normalization, reduction + counter init. One warp per row.
// ---------------------------------------------------------------------------
__global__ void prep_kernel(const float* __restrict__ feat,
                            const int* __restrict__ lab_raw, int n) {
    int row  = blockIdx.x * 8 + (threadIdx.x >> 5);
    int lane = threadIdx.x & 31;
    if (row >= n) return;

    const float4* p = (const float4*)(feat + (size_t)row * DIMK);
    float4 v0 = p[2 * lane];
    float4 v1 = p[2 * lane + 1];

    float s = v0.x * v0.x + v0.y * v0.y + v0.z * v0.z + v0.w * v0.w
            + v1.x * v1.x + v1.y * v1.y + v1.z * v1.z + v1.w * v1.w;

    __half2 h0 = __floats2half2_rn(v0.x, v0.y);
    __half2 h1 = __floats2half2_rn(v0.z, v0.w);
    __half2 h2 = __floats2half2_rn(v1.x, v1.y);
    __half2 h3 = __floats2half2_rn(v1.z, v1.w);
    uint4 pk;
    pk.x = *(uint32_t*)&h0; pk.y = *(uint32_t*)&h1;
    pk.z = *(uint32_t*)&h2; pk.w = *(uint32_t*)&h3;

    const int blk = row >> 7;
    const int c   = lane >> 3;
    const uint32_t in_off = SWZ(((uint32_t)(row & 127)) * 128 + (lane & 7) * 16);
    char* dst = (char*)g_f16s + (((size_t)blk * NSC + c) << 14) + in_off;
    *(uint4*)dst = pk;

#pragma unroll
    for (int o = 16; o; o >>= 1) s += __shfl_xor_sync(0xffffffffu, s, o);

    if (lane == 0) {
        g_xx[row]     = s;
        g_posmax[row] = 0;
        g_negmin[row] = __float_as_int(FLT_MAX);
    }
    if (lane == 1) {
        bool is64 = true;
#pragma unroll
        for (int i = 0; i < 32; i++)
            if (lab_raw[2 * i + 1] != 0) { is64 = false; break; }
        g_lab[row] = is64 ? lab_raw[2 * row] : lab_raw[row];
    }
    if (row == 0 && lane == 2) g_done = 0;
}

// ---------------------------------------------------------------------------
// Supertile enumeration: (ti, sj), sj covers j-blocks {2sj, 2sj+1}, kept if
// 2sj+1 >= ti. Duplicate transpose halves harmless (max/min idempotent).
// Count = 272 for ntb=32.
// ---------------------------------------------------------------------------
__device__ __forceinline__ void decode_st(int t, int nsb, int& ti, int& sj) {
    ti = 0;
    while (t >= nsb - (ti >> 1)) { t -= nsb - (ti >> 1); ti++; }
    sj = (ti >> 1) + t;
}

// Refill one big-chunk (128 kcols): A + B0 + B1, three 32KB bulk copies.
__device__ __forceinline__ void issue_bigchunk(uint32_t st, uint32_t fb,
                                               int ti, int sj, int c2) {
    MBAR_EXPECT_TX(fb, 3 * BLOCK_BYTES);
    const char* A  = (const char*)g_f16s + ((((size_t)ti)           * NSC + c2 * 2) << 14);
    const char* B0 = (const char*)g_f16s + ((((size_t)(2 * sj))     * NSC + c2 * 2) << 14);
    const char* B1 = (const char*)g_f16s + ((((size_t)(2 * sj + 1)) * NSC + c2 * 2) << 14);
    bulk_g2s(st,                   A,  fb);
    bulk_g2s(st + BLOCK_BYTES,     B0, fb);
    bulk_g2s(st + 2 * BLOCK_BYTES, B1, fb);
}

// MMA over one 128-kcol big-chunk, per-warp 32x32 output.
__device__ __forceinline__ void mma_bigchunk(float acc[2][4][4], uint32_t st,
                                             int m_base, int n_base, int lane) {
    const uint32_t sA = st;
    const uint32_t sB = st + BLOCK_BYTES + ((uint32_t)(n_base >> 7)) * BLOCK_BYTES;
    const int nloc = n_base & 127;               // 0/32/64/96 within B block
#pragma unroll
    for (int s8 = 0; s8 < 8; s8++) {
        const int sc = s8 >> 2, ks = s8 & 3;
        const uint32_t so = (uint32_t)sc * SUB_BYTES;
        const uint32_t koff = (uint32_t)ks * 32 + ((lane >> 4) << 4);
        uint32_t a[2][4], b[2][4];
#pragma unroll
        for (int mt = 0; mt < 2; mt++) {
            uint32_t ad = SWZ((uint32_t)(m_base + mt * 16 + (lane & 15)) * 128 + koff);
            ldsm4(a[mt], sA + so + ad);
        }
#pragma unroll
        for (int p = 0; p < 2; p++) {
            uint32_t bd = SWZ((uint32_t)(nloc + p * 16 + (lane & 15)) * 128 + koff);
            ldsm4(b[p], sB + so + bd);
        }
#pragma unroll
        for (int mt = 0; mt < 2; mt++)
#pragma unroll
            for (int nt = 0; nt < 4; nt++) {
                const int p = nt >> 1, q = nt & 1;
                mma16816(acc[mt][nt], a[mt], b[p][q], b[p][2 + q]);
            }
    }
}

// ---------------------------------------------------------------------------
// Persistent kernel: 128x256 supertiles, 32 warps of 32x32 (8/SMSP),
// 2-stage 96KB ring, early producer, fused final reduction.
// ---------------------------------------------------------------------------
__global__ void __launch_bounds__(NTHR, 1) tile_kernel(float* __restrict__ out, int n) {
    extern __shared__ char smem_raw[];
    uint32_t sb_raw = s2u(smem_raw);
    uint32_t pad = (1024u - (sb_raw & 1023u)) & 1023u;
    char* sm = smem_raw + pad;
    uint32_t sb = sb_raw + pad;

    float* xxi_s  = (float*)(sm + SM_XXI);
    int*   labi_s = (int*)(sm + SM_LABI);
    float* xxj_s  = (float*)(sm + SM_XXJ);
    int*   labj_s = (int*)(sm + SM_LABJ);

    const int tid = threadIdx.x, lane = tid & 31, w = tid >> 5;
    const int m_base = (w & 3) * 32;     // 4 warps along M (128 rows)
    const int n_base = (w >> 2) * 32;    // 8 warps along N (256 cols)

    const int ntb = n >> 7;
    const int nsb = ntb >> 1;
    int ST = 0;
    for (int t2 = 0; t2 < ntb; t2++) ST += nsb - (t2 >> 1);
    const int myST = (ST - (int)blockIdx.x + (int)gridDim.x - 1) / (int)gridDim.x;
    const int G    = myST * 2;

    if (tid == 0) {
#pragma unroll
        for (int s = 0; s < NSTG; s++) {
            MBAR_INIT(sb + SM_FULL + s * 8, 1);
            MBAR_INIT(sb + SM_EMPTY + s * 8, 32);
        }
    }
    __syncthreads();

    if (G > 0) {
        int ti0, sj0;
        decode_st(blockIdx.x, nsb, ti0, sj0);
        if (tid == 0) {
            issue_bigchunk(sb + SM_STAGE,            sb + SM_FULL,     ti0, sj0, 0);
            issue_bigchunk(sb + SM_STAGE + STAGE_SZ, sb + SM_FULL + 8, ti0, sj0, 1);
        }

        float acc[2][4][4];
        int ti = ti0, sj = sj0;

        for (int g = 0; g < G; g++) {
            const int s = g & 1;

            if ((g & 1) == 0) {
                if (g > 0) decode_st((int)blockIdx.x + (g >> 1) * (int)gridDim.x,
                                     nsb, ti, sj);
                __syncthreads();                   // prev epilogue done reading
                if (tid < 128) {
                    xxi_s[tid]  = g_xx[ti * 128 + tid];
                    labi_s[tid] = g_lab[ti * 128 + tid];
                } else if (tid < 384) {
                    int q = tid - 128;
                    xxj_s[q]  = g_xx[sj * 256 + q];
                    labj_s[q] = g_lab[sj * 256 + q];
                }
                __syncthreads();
#pragma unroll
                for (int a = 0; a < 2; a++)
#pragma unroll
                    for (int b = 0; b < 4; b++)
#pragma unroll
                        for (int e = 0; e < 4; e++) acc[a][b][e] = 0.f;
            }

            // early producer: refill the OTHER stage (released at chunk g-1)
            if (tid == 0 && g >= 1 && g + 1 < G) {
                uint32_t ep = (uint32_t)((((g + 1) >> 1) - 1) & 1);
                mbar_wait(sb + SM_EMPTY + (s ^ 1) * 8, ep);
                FENCE_ASYNC();
                int lti, lsj;
                decode_st((int)blockIdx.x + ((g + 1) >> 1) * (int)gridDim.x,
                          nsb, lti, lsj);
                issue_bigchunk(sb + SM_STAGE + (s ^ 1) * STAGE_SZ,
                               sb + SM_FULL + (s ^ 1) * 8, lti, lsj, (g + 1) & 1);
            }

            mbar_wait(sb + SM_FULL + s * 8, (uint32_t)((g >> 1) & 1));
            mma_bigchunk(acc, sb + SM_STAGE + s * STAGE_SZ, m_base, n_base, lane);
            if (lane == 0) MBAR_ARRIVE(sb + SM_EMPTY + s * 8);

            if ((g & 1) == 1) {
                // ---- epilogue over this warp's 32x32 block ----
                float xi[4]; int li[4];
#pragma unroll
                for (int mt = 0; mt < 2; mt++)
#pragma unroll
                    for (int rh = 0; rh < 2; rh++) {
                        int r = m_base + mt * 16 + (lane >> 2) + 8 * rh;
                        xi[mt * 2 + rh] = xxi_s[r];
                        li[mt * 2 + rh] = labi_s[r];
                    }
                float xj[8]; int lj[8];
#pragma unroll
                for (int nt = 0; nt < 4; nt++)
#pragma unroll
                    for (int cc = 0; cc < 2; cc++) {
                        int q = n_base + nt * 8 + (lane & 3) * 2 + cc;
                        xj[nt * 2 + cc] = xxj_s[q];
                        lj[nt * 2 + cc] = labj_s[q];
                    }
#pragma unroll
                for (int mt = 0; mt < 2; mt++)
#pragma unroll
                    for (int nt = 0; nt < 4; nt++)
#pragma unroll
                        for (int e = 0; e < 4; e++) {
                            int rh = e >> 1, cc = e & 1;
                            acc[mt][nt][e] = fmaf(-2.f, acc[mt][nt][e],
                                                  xi[mt * 2 + rh] + xj[nt * 2 + cc]);
                        }

                // row direction
#pragma unroll
                for (int mt = 0; mt < 2; mt++)
#pragma unroll
                    for (int rh = 0; rh < 2; rh++) {
                        float pm = -1.f, nm = FLT_MAX;
                        const int L = li[mt * 2 + rh];
#pragma unroll
                        for (int nt = 0; nt < 4; nt++)
#pragma unroll
                            for (int cc = 0; cc < 2; cc++) {
                                float v = acc[mt][nt][rh * 2 + cc];
                                if (L == lj[nt * 2 + cc]) pm = fmaxf(pm, v);
                                else                      nm = fminf(nm, v);
                            }
                        pm = fmaxf(pm, __shfl_xor_sync(0xffffffffu, pm, 1));
                        pm = fmaxf(pm, __shfl_xor_sync(0xffffffffu, pm, 2));
                        nm = fminf(nm, __shfl_xor_sync(0xffffffffu, nm, 1));
                        nm = fminf(nm, __shfl_xor_sync(0xffffffffu, nm, 2));
                        if ((lane & 3) == 0) {
                            int gi = ti * 128 + m_base + mt * 16 + (lane >> 2) + 8 * rh;
                            atomicMax(&g_posmax[gi], __float_as_int(pm));
                            atomicMin(&g_negmin[gi], __float_as_int(nm));
                        }
                    }

                // column direction (symmetry)
#pragma unroll
                for (int nt = 0; nt < 4; nt++)
#pragma unroll
                    for (int cc = 0; cc < 2; cc++) {
                        float pm = -1.f, nm = FLT_MAX;
                        const int L = lj[nt * 2 + cc];
#pragma unroll
                        for (int mt = 0; mt < 2; mt++)
#pragma unroll
                            for (int rh = 0; rh < 2; rh++) {
                                float v = acc[mt][nt][rh * 2 + cc];
                                if (L == li[mt * 2 + rh]) pm = fmaxf(pm, v);
                                else                      nm = fminf(nm, v);
                            }
                        pm = fmaxf(pm, __shfl_xor_sync(0xffffffffu, pm, 4));
                        pm = fmaxf(pm, __shfl_xor_sync(0xffffffffu, pm, 8));
                        pm = fmaxf(pm, __shfl_xor_sync(0xffffffffu, pm, 16));
                        nm = fminf(nm, __shfl_xor_sync(0xffffffffu, nm, 4));
                        nm = fminf(nm, __shfl_xor_sync(0xffffffffu, nm, 8));
                        nm = fminf(nm, __shfl_xor_sync(0xffffffffu, nm, 16));
                        if (lane < 4) {
                            int gj = sj * 256 + n_base + nt * 8 + (lane & 3) * 2 + cc;
                            atomicMax(&g_posmax[gj], __float_as_int(pm));
                            atomicMin(&g_negmin[gj], __float_as_int(nm));
                        }
                    }
            }
        }
    }

    // ---- completion counter: last CTA performs the finalize reduction ----
    __syncthreads();
    if (tid == 0) {
        __threadfence();
        int prev = atomicAdd(&g_done, 1);
        *(volatile int*)(sm + SM_FLAG) = (prev == (int)gridDim.x - 1) ? 1 : 0;
    }
    __syncthreads();
    if (*(volatile int*)(sm + SM_FLAG)) {
        float* ss = (float*)(sm + SM_STAGE);
        float* sc = ss + NTHR;
        float sum = 0.f, cnt = 0.f;
        for (int i = tid; i < n; i += NTHR) {
            float ap2 = __int_as_float(ldcg_i(&g_posmax[i]));
            float ap  = sqrtf(fmaxf(ap2, 1e-12f));
            float nm2 = __int_as_float(ldcg_i(&g_negmin[i]));
            bool  has_neg = nm2 < 1e30f;
            float an  = has_neg ? sqrtf(fmaxf(nm2, 1e-12f)) : 0.f;
            bool  valid = (ap < 1000000.0f) && (an > 0.f);
            if (valid) {
                sum += fmaxf(0.3f + ap - an, 0.f);
                cnt += 1.f;
            }
        }
        ss[tid] = sum;
        sc[tid] = cnt;
        __syncthreads();
        for (int o = NTHR / 2; o; o >>= 1) {
            if (tid < o) {
                ss[tid] += ss[tid + o];
                sc[tid] += sc[tid + o];
            }
            __syncthreads();
        }
        if (tid == 0)
            out[0] = (sc[0] > 0.f) ? ss[0] / fmaxf(sc[0], 1.f) : 0.f;
    }
}

// ---------------------------------------------------------------------------
extern "C" void kernel_launch(void* const* d_in, const int* in_sizes, int n_in,
                              void* d_out, int out_size) {
    const float* feat   = (const float*)d_in[0];
    const int*   labels = (const int*)d_in[1];   // int32/int64 auto-detected
    int n = in_sizes[1];                         // 4096

    cudaFuncSetAttribute(tile_kernel, cudaFuncAttributeMaxDynamicSharedMemorySize,
                         SMEM_TOTAL);

    prep_kernel<<<(n + 7) / 8, 256>>>(feat, labels, n);
    tile_kernel<<<148, NTHR, SMEM_TOTAL>>>((float*)d_out, n);
}

// round 15
// speedup vs baseline: 1.3428x; 1.1553x over previous
#include <cuda_runtime.h>
#include <float.h>
#include <stdint.h>

#define NMAX 4096
#define DIMK 256              // fp32 features per row
#define NSC  2                // 16KB sub-chunks per 128-row block (128 int8 kcols each)
#define NSTG 2                // smem pipeline stages
#define NTHR 512
#define SUB_BYTES 16384       // one 128x128 int8 sub-chunk, pre-swizzled

// ---------------- device scratch (no allocs allowed) ----------------
__device__ int    g_posmax[NMAX];                // max d^2 over positives, float bits
__device__ int    g_negmin[NMAX];                // min d^2 over negatives, float bits
__device__ float  g_xx[NMAX];                    // squared norms (exact fp32)
__device__ float  g_sc[NMAX];                    // per-row quant scale
__device__ int    g_lab[NMAX];                   // normalized labels
__device__ int    g_done;
// chunk-major pre-swizzled int8 features:
// block b = row/128, sub-chunk c = col/128 -> contiguous 16KB at ((b*2+c)<<14)
__device__ __align__(16) int8_t g_i8s[NMAX * DIMK];

// ---------------- PTX helpers (sm_90-baseline ISA) ----------------
__device__ __forceinline__ uint32_t s2u(const void* p) {
    uint32_t a;
    asm("{ .reg .u64 t; cvta.to.shared.u64 t, %1; cvt.u32.u64 %0, t; }" : "=r"(a) : "l"(p));
    return a;
}
#define MBAR_INIT(a, c) asm volatile("mbarrier.init.shared.b64 [%0], %1;" :: "r"(a), "r"(c) : "memory")
#define MBAR_EXPECT_TX(a, b) asm volatile("mbarrier.arrive.expect_tx.shared.b64 _, [%0], %1;" :: "r"(a), "r"(b) : "memory")
#define MBAR_ARRIVE(a) asm volatile("mbarrier.arrive.release.cta.shared.b64 _, [%0];" :: "r"(a) : "memory")
#define FENCE_ASYNC()  asm volatile("fence.proxy.async.shared::cta;" ::: "memory")
__device__ __forceinline__ void mbar_wait(uint32_t mbar, uint32_t parity) {
    asm volatile(
        "{\n\t.reg .pred P;\n\t"
        "WL_%=:\n\t"
        "mbarrier.try_wait.parity.acquire.cta.shared::cta.b64 P, [%0], %1, 0x989680;\n\t"
        "@!P bra WL_%=;\n\t}"
        :: "r"(mbar), "r"(parity) : "memory");
}
__device__ __forceinline__ void bulk_g2s(uint32_t dst, const void* src, uint32_t mbar) {
    asm volatile(
        "cp.async.bulk.shared::cluster.global.mbarrier::complete_tx::bytes "
        "[%0], [%1], %2, [%3];"
        :: "r"(dst), "l"(src), "r"((uint32_t)SUB_BYTES), "r"(mbar) : "memory");
}
__device__ __forceinline__ void ldsm4(uint32_t* r, uint32_t a) {
    asm volatile("ldmatrix.sync.aligned.m8n8.x4.shared.b16 {%0,%1,%2,%3}, [%4];"
                 : "=r"(r[0]), "=r"(r[1]), "=r"(r[2]), "=r"(r[3]) : "r"(a));
}
// int8 k32 MMA: byte-layout identical to f16 k16 (16 rows x 32B fragments)
__device__ __forceinline__ void mma_s8(int* d, const uint32_t* a,
                                       uint32_t b0, uint32_t b1) {
    asm volatile(
        "mma.sync.aligned.m16n8k32.row.col.s32.s8.s8.s32 "
        "{%0,%1,%2,%3}, {%4,%5,%6,%7}, {%8,%9}, {%0,%1,%2,%3};"
        : "+r"(d[0]), "+r"(d[1]), "+r"(d[2]), "+r"(d[3])
        : "r"(a[0]), "r"(a[1]), "r"(a[2]), "r"(a[3]), "r"(b0), "r"(b1));
}
__device__ __forceinline__ int ldcg_i(const int* p) {
    int v; asm volatile("ld.global.cg.s32 %0, [%1];" : "=r"(v) : "l"(p)); return v;
}
#define SWZ(x) ((x) ^ ((((uint32_t)(x)) >> 3) & 0x70))

// SMEM layout (relative to 1024-aligned base)
#define SM_FULL   0           // 2 x 8B mbarriers
#define SM_EMPTY  64          // 2 x 8B mbarriers
#define SM_FLAG   128
#define SM_XXI    256         // 128 float
#define SM_LABI   768         // 128 int
#define SM_SCI    1280        // 128 float
#define SM_XXJ    1792        // 256 float
#define SM_LABJ   2816        // 256 int
#define SM_SCJ    3840        // 256 float
#define SM_STAGE  5120        // 2 stages x 48KB: A(16K) | B0(16K) | B1(16K)
#define STAGE_SZ  49152
#define SMEM_TOTAL (SM_STAGE + NSTG * STAGE_SZ + 16384)  // padded -> 1 CTA/SM

// ---------------------------------------------------------------------------
// Prep: int8 quantize (per-row scale) into chunk-major PRE-SWIZZLED layout,
// exact fp32 norms, scales, labels, init. One warp per row.
// ---------------------------------------------------------------------------
__global__ void prep_kernel(const float* __restrict__ feat,
                            const int* __restrict__ lab_raw, int n) {
    int row  = blockIdx.x * 8 + (threadIdx.x >> 5);
    int lane = threadIdx.x & 31;
    if (row >= n) return;

    const float4* p = (const float4*)(feat + (size_t)row * DIMK);
    float4 v0 = p[2 * lane];          // cols lane*8 .. lane*8+3
    float4 v1 = p[2 * lane + 1];      // cols lane*8+4 .. lane*8+7

    float s = v0.x * v0.x + v0.y * v0.y + v0.z * v0.z + v0.w * v0.w
            + v1.x * v1.x + v1.y * v1.y + v1.z * v1.z + v1.w * v1.w;
    float m = fmaxf(fmaxf(fmaxf(fabsf(v0.x), fabsf(v0.y)), fmaxf(fabsf(v0.z), fabsf(v0.w))),
                    fmaxf(fmaxf(fabsf(v1.x), fabsf(v1.y)), fmaxf(fabsf(v1.z), fabsf(v1.w))));
#pragma unroll
    for (int o = 16; o; o >>= 1) {
        s += __shfl_xor_sync(0xffffffffu, s, o);
        m = fmaxf(m, __shfl_xor_sync(0xffffffffu, m, o));
    }
    const float inv = (m > 0.f) ? 127.f / m : 0.f;

    // quantize 8 values -> 8 bytes
    float vv[8] = {v0.x, v0.y, v0.z, v0.w, v1.x, v1.y, v1.z, v1.w};
    uint8_t qb[8];
#pragma unroll
    for (int k = 0; k < 8; k++) {
        int q = __float2int_rn(vv[k] * inv);
        q = max(-127, min(127, q));
        qb[k] = (uint8_t)(int8_t)q;
    }
    uint64_t pk;
    memcpy(&pk, qb, 8);

    const int blk = row >> 7;
    const int c   = lane >> 4;                 // sub-chunk = (lane*8)/128
    const uint32_t gr = SWZ(((uint32_t)(row & 127)) * 128 + (((lane & 15) >> 1) << 4))
                      + (uint32_t)(lane & 1) * 8;
    char* dst = (char*)g_i8s + (((size_t)blk * NSC + c) << 14) + gr;
    *(uint64_t*)dst = pk;

    if (lane == 0) {
        g_xx[row]     = s;
        g_sc[row]     = (m > 0.f) ? m / 127.f : 0.f;
        g_posmax[row] = 0;
        g_negmin[row] = __float_as_int(FLT_MAX);
    }
    if (lane == 1) {
        bool is64 = true;
#pragma unroll
        for (int i = 0; i < 32; i++)
            if (lab_raw[2 * i + 1] != 0) { is64 = false; break; }
        g_lab[row] = is64 ? lab_raw[2 * row] : lab_raw[row];
    }
    if (row == 0 && lane == 2) g_done = 0;
}

// ---------------------------------------------------------------------------
// Supertile enumeration (identical to R10): (ti, sj), sj covers {2sj, 2sj+1}.
// ---------------------------------------------------------------------------
__device__ __forceinline__ void decode_st(int t, int nsb, int& ti, int& sj) {
    ti = 0;
    while (t >= nsb - (ti >> 1)) { t -= nsb - (ti >> 1); ti++; }
    sj = (ti >> 1) + t;
}

// Refill one big-chunk (128 int8 kcols): A + B0 + B1, three 16KB bulk copies.
__device__ __forceinline__ void issue_bigchunk(uint32_t st, uint32_t fb,
                                               int ti, int sj, int c2) {
    MBAR_EXPECT_TX(fb, 3 * SUB_BYTES);
    const char* A  = (const char*)g_i8s + ((((size_t)ti)           * NSC + c2) << 14);
    const char* B0 = (const char*)g_i8s + ((((size_t)(2 * sj))     * NSC + c2) << 14);
    const char* B1 = (const char*)g_i8s + ((((size_t)(2 * sj + 1)) * NSC + c2) << 14);
    bulk_g2s(st,                 A,  fb);
    bulk_g2s(st + SUB_BYTES,     B0, fb);
    bulk_g2s(st + 2 * SUB_BYTES, B1, fb);
}

// MMA over one 128-kcol int8 big-chunk, per-warp 32x64 output (s32 acc).
__device__ __forceinline__ void mma_bigchunk(int acc[2][8][4], uint32_t st,
                                             int m_base, int n_base, int lane) {
    const uint32_t sA = st;
    const uint32_t sB = st + SUB_BYTES + ((uint32_t)(n_base >> 7)) * SUB_BYTES;
    const int nloc = n_base & 127;               // 0 or 64 within B block
#pragma unroll
    for (int ks = 0; ks < 4; ks++) {              // k32 steps within 128 kcols
        const uint32_t koff = (uint32_t)ks * 32 + ((lane >> 4) << 4);
        uint32_t a[2][4], b[4][4];
#pragma unroll
        for (int mt = 0; mt < 2; mt++) {
            uint32_t ad = SWZ((uint32_t)(m_base + mt * 16 + (lane & 15)) * 128 + koff);
            ldsm4(a[mt], sA + ad);
        }
#pragma unroll
        for (int p = 0; p < 4; p++) {
            uint32_t bd = SWZ((uint32_t)(nloc + p * 16 + (lane & 15)) * 128 + koff);
            ldsm4(b[p], sB + bd);
        }
#pragma unroll
        for (int mt = 0; mt < 2; mt++)
#pragma unroll
            for (int nt = 0; nt < 8; nt++) {
                const int p = nt >> 1, q = nt & 1;
                mma_s8(acc[mt][nt], a[mt], b[p][q], b[p][2 + q]);
            }
    }
}

// ---------------------------------------------------------------------------
// Persistent kernel: 128x256 supertiles, 16 warps of 32x64, 2-stage 48KB ring,
// early producer, scaled-int8 epilogue, fused final reduction.
// ---------------------------------------------------------------------------
__global__ void __launch_bounds__(NTHR, 1) tile_kernel(float* __restrict__ out, int n) {
    extern __shared__ char smem_raw[];
    uint32_t sb_raw = s2u(smem_raw);
    uint32_t pad = (1024u - (sb_raw & 1023u)) & 1023u;
    char* sm = smem_raw + pad;
    uint32_t sb = sb_raw + pad;

    float* xxi_s  = (float*)(sm + SM_XXI);
    int*   labi_s = (int*)(sm + SM_LABI);
    float* sci_s  = (float*)(sm + SM_SCI);
    float* xxj_s  = (float*)(sm + SM_XXJ);
    int*   labj_s = (int*)(sm + SM_LABJ);
    float* scj_s  = (float*)(sm + SM_SCJ);

    const int tid = threadIdx.x, lane = tid & 31, w = tid >> 5;
    const int m_base = (w & 3) * 32;     // 4 warps along M (128 rows)
    const int n_base = (w >> 2) * 64;    // 4 warps along N (256 cols)

    const int ntb = n >> 7;
    const int nsb = ntb >> 1;
    int ST = 0;
    for (int t2 = 0; t2 < ntb; t2++) ST += nsb - (t2 >> 1);
    const int myST = (ST - (int)blockIdx.x + (int)gridDim.x - 1) / (int)gridDim.x;
    const int G    = myST * 2;

    if (tid == 0) {
#pragma unroll
        for (int s = 0; s < NSTG; s++) {
            MBAR_INIT(sb + SM_FULL + s * 8, 1);
            MBAR_INIT(sb + SM_EMPTY + s * 8, 16);
        }
    }
    __syncthreads();

    if (G > 0) {
        int ti0, sj0;
        decode_st(blockIdx.x, nsb, ti0, sj0);
        if (tid == 0) {
            issue_bigchunk(sb + SM_STAGE,            sb + SM_FULL,     ti0, sj0, 0);
            issue_bigchunk(sb + SM_STAGE + STAGE_SZ, sb + SM_FULL + 8, ti0, sj0, 1);
        }

        int acc[2][8][4];
        int ti = ti0, sj = sj0;

        for (int g = 0; g < G; g++) {
            const int s = g & 1;

            if ((g & 1) == 0) {
                if (g > 0) decode_st((int)blockIdx.x + (g >> 1) * (int)gridDim.x,
                                     nsb, ti, sj);
                __syncthreads();                   // prev epilogue done reading
                if (tid < 128) {
                    xxi_s[tid]  = g_xx[ti * 128 + tid];
                    labi_s[tid] = g_lab[ti * 128 + tid];
                    sci_s[tid]  = g_sc[ti * 128 + tid];
                } else if (tid < 384) {
                    int q = tid - 128;
                    xxj_s[q]  = g_xx[sj * 256 + q];
                    labj_s[q] = g_lab[sj * 256 + q];
                    scj_s[q]  = g_sc[sj * 256 + q];
                }
                __syncthreads();
#pragma unroll
                for (int a = 0; a < 2; a++)
#pragma unroll
                    for (int b = 0; b < 8; b++)
#pragma unroll
                        for (int e = 0; e < 4; e++) acc[a][b][e] = 0;
            }

            // early producer: refill the OTHER stage (released at chunk g-1)
            if (tid == 0 && g >= 1 && g + 1 < G) {
                uint32_t ep = (uint32_t)((((g + 1) >> 1) - 1) & 1);
                mbar_wait(sb + SM_EMPTY + (s ^ 1) * 8, ep);
                FENCE_ASYNC();
                int lti, lsj;
                decode_st((int)blockIdx.x + ((g + 1) >> 1) * (int)gridDim.x,
                          nsb, lti, lsj);
                issue_bigchunk(sb + SM_STAGE + (s ^ 1) * STAGE_SZ,
                               sb + SM_FULL + (s ^ 1) * 8, lti, lsj, (g + 1) & 1);
            }

            mbar_wait(sb + SM_FULL + s * 8, (uint32_t)((g >> 1) & 1));
            mma_bigchunk(acc, sb + SM_STAGE + s * STAGE_SZ, m_base, n_base, lane);
            if (lane == 0) MBAR_ARRIVE(sb + SM_EMPTY + s * 8);

            if ((g & 1) == 1) {
                // ---- epilogue: d^2 = xx_i + xx_j - 2 s_i s_j dotq ----
                float xi[4], m2si[4]; int li[4];
#pragma unroll
                for (int mt = 0; mt < 2; mt++)
#pragma unroll
                    for (int rh = 0; rh < 2; rh++) {
                        int r = m_base + mt * 16 + (lane >> 2) + 8 * rh;
                        xi[mt * 2 + rh]   = xxi_s[r];
                        li[mt * 2 + rh]   = labi_s[r];
                        m2si[mt * 2 + rh] = -2.f * sci_s[r];
                    }
                float xj[16], sjv[16]; int lj[16];
#pragma unroll
                for (int nt = 0; nt < 8; nt++)
#pragma unroll
                    for (int cc = 0; cc < 2; cc++) {
                        int q = n_base + nt * 8 + (lane & 3) * 2 + cc;
                        xj[nt * 2 + cc]  = xxj_s[q];
                        lj[nt * 2 + cc]  = labj_s[q];
                        sjv[nt * 2 + cc] = scj_s[q];
                    }
                float d2v[2][8][4];
#pragma unroll
                for (int mt = 0; mt < 2; mt++)
#pragma unroll
                    for (int nt = 0; nt < 8; nt++)
#pragma unroll
                        for (int e = 0; e < 4; e++) {
                            int rh = e >> 1, cc = e & 1;
                            d2v[mt][nt][e] = fmaf(m2si[mt * 2 + rh] * sjv[nt * 2 + cc],
                                                  (float)acc[mt][nt][e],
                                                  xi[mt * 2 + rh] + xj[nt * 2 + cc]);
                        }

                // row direction
#pragma unroll
                for (int mt = 0; mt < 2; mt++)
#pragma unroll
                    for (int rh = 0; rh < 2; rh++) {
                        float pm = -1.f, nm = FLT_MAX;
                        const int L = li[mt * 2 + rh];
#pragma unroll
                        for (int nt = 0; nt < 8; nt++)
#pragma unroll
                            for (int cc = 0; cc < 2; cc++) {
                                float v = d2v[mt][nt][rh * 2 + cc];
                                if (L == lj[nt * 2 + cc]) pm = fmaxf(pm, v);
                                else                      nm = fminf(nm, v);
                            }
                        pm = fmaxf(pm, __shfl_xor_sync(0xffffffffu, pm, 1));
                        pm = fmaxf(pm, __shfl_xor_sync(0xffffffffu, pm, 2));
                        nm = fminf(nm, __shfl_xor_sync(0xffffffffu, nm, 1));
                        nm = fminf(nm, __shfl_xor_sync(0xffffffffu, nm, 2));
                        if ((lane & 3) == 0) {
                            int gi = ti * 128 + m_base + mt * 16 + (lane >> 2) + 8 * rh;
                            atomicMax(&g_posmax[gi], __float_as_int(pm));
                            atomicMin(&g_negmin[gi], __float_as_int(nm));
                        }
                    }

                // column direction (symmetry)
#pragma unroll
                for (int nt = 0; nt < 8; nt++)
#pragma unroll
                    for (int cc = 0; cc < 2; cc++) {
                        float pm = -1.f, nm = FLT_MAX;
                        const int L = lj[nt * 2 + cc];
#pragma unroll
                        for (int mt = 0; mt < 2; mt++)
#pragma unroll
                            for (int rh = 0; rh < 2; rh++) {
                                float v = d2v[mt][nt][rh * 2 + cc];
                                if (L == li[mt * 2 + rh]) pm = fmaxf(pm, v);
                                else                      nm = fminf(nm, v);
                            }
                        pm = fmaxf(pm, __shfl_xor_sync(0xffffffffu, pm, 4));
                        pm = fmaxf(pm, __shfl_xor_sync(0xffffffffu, pm, 8));
                        pm = fmaxf(pm, __shfl_xor_sync(0xffffffffu, pm, 16));
                        nm = fminf(nm, __shfl_xor_sync(0xffffffffu, nm, 4));
                        nm = fminf(nm, __shfl_xor_sync(0xffffffffu, nm, 8));
                        nm = fminf(nm, __shfl_xor_sync(0xffffffffu, nm, 16));
                        if (lane < 4) {
                            int gj = sj * 256 + n_base + nt * 8 + (lane & 3) * 2 + cc;
                            atomicMax(&g_posmax[gj], __float_as_int(pm));
                            atomicMin(&g_negmin[gj], __float_as_int(nm));
                        }
                    }
            }
        }
    }

    // ---- completion counter: last CTA performs the finalize reduction ----
    __syncthreads();
    if (tid == 0) {
        __threadfence();
        int prev = atomicAdd(&g_done, 1);
        *(volatile int*)(sm + SM_FLAG) = (prev == (int)gridDim.x - 1) ? 1 : 0;
    }
    __syncthreads();
    if (*(volatile int*)(sm + SM_FLAG)) {
        float* ss = (float*)(sm + SM_STAGE);
        float* sc = ss + NTHR;
        float sum = 0.f, cnt = 0.f;
        for (int i = tid; i < n; i += NTHR) {
            float ap2 = __int_as_float(ldcg_i(&g_posmax[i]));
            float ap  = sqrtf(fmaxf(ap2, 1e-12f));
            float nm2 = __int_as_float(ldcg_i(&g_negmin[i]));
            bool  has_neg = nm2 < 1e30f;
            float an  = has_neg ? sqrtf(fmaxf(nm2, 1e-12f)) : 0.f;
            bool  valid = (ap < 1000000.0f) && (an > 0.f);
            if (valid) {
                sum += fmaxf(0.3f + ap - an, 0.f);
                cnt += 1.f;
            }
        }
        ss[tid] = sum;
        sc[tid] = cnt;
        __syncthreads();
        for (int o = NTHR / 2; o; o >>= 1) {
            if (tid < o) {
                ss[tid] += ss[tid + o];
                sc[tid] += sc[tid + o];
            }
            __syncthreads();
        }
        if (tid == 0)
            out[0] = (sc[0] > 0.f) ? ss[0] / fmaxf(sc[0], 1.f) : 0.f;
    }
}

// ---------------------------------------------------------------------------
extern "C" void kernel_launch(void* const* d_in, const int* in_sizes, int n_in,
                              void* d_out, int out_size) {
    const float* feat   = (const float*)d_in[0];
    const int*   labels = (const int*)d_in[1];   // int32/int64 auto-detected
    int n = in_sizes[1];                         // 4096

    cudaFuncSetAttribute(tile_kernel, cudaFuncAttributeMaxDynamicSharedMemorySize,
                         SMEM_TOTAL);

    prep_kernel<<<(n + 7) / 8, 256>>>(feat, labels, n);
    tile_kernel<<<148, NTHR, SMEM_TOTAL>>>((float*)d_out, n);
}

// round 16
// speedup vs baseline: 1.4219x; 1.0589x over previous
#include <cuda_runtime.h>
#include <float.h>
#include <stdint.h>

#define NMAX 4096
#define DIMK 256              // fp32 features per row
#define NSC  2                // 16KB sub-chunks per 128-row block (128 int8 kcols each)
#define NSTG 2                // smem pipeline stages (1 supertile per stage)
#define NTHR 512
#define SUB_BYTES   16384     // one 128x128 int8 sub-chunk, pre-swizzled
#define BLOCK_BYTES 32768     // full 128x256 int8 block (2 contiguous sub-chunks)

// ---------------- device scratch (no allocs allowed) ----------------
__device__ int    g_posmax[NMAX];                // max d^2 over positives, float bits
__device__ int    g_negmin[NMAX];                // min d^2 over negatives, float bits
__device__ float  g_xx[NMAX];                    // squared norms (exact fp32)
__device__ float  g_sc[NMAX];                    // per-row quant scale
__device__ int    g_lab[NMAX];                   // normalized labels
__device__ int    g_done;
// chunk-major pre-swizzled int8 features:
// block b = row/128, sub-chunk c = col/128 -> contiguous 16KB at ((b*2+c)<<14)
__device__ __align__(16) int8_t g_i8s[NMAX * DIMK];

// ---------------- PTX helpers (sm_90-baseline ISA) ----------------
__device__ __forceinline__ uint32_t s2u(const void* p) {
    uint32_t a;
    asm("{ .reg .u64 t; cvta.to.shared.u64 t, %1; cvt.u32.u64 %0, t; }" : "=r"(a) : "l"(p));
    return a;
}
#define MBAR_INIT(a, c) asm volatile("mbarrier.init.shared.b64 [%0], %1;" :: "r"(a), "r"(c) : "memory")
#define MBAR_EXPECT_TX(a, b) asm volatile("mbarrier.arrive.expect_tx.shared.b64 _, [%0], %1;" :: "r"(a), "r"(b) : "memory")
#define MBAR_ARRIVE(a) asm volatile("mbarrier.arrive.release.cta.shared.b64 _, [%0];" :: "r"(a) : "memory")
#define FENCE_ASYNC()  asm volatile("fence.proxy.async.shared::cta;" ::: "memory")
__device__ __forceinline__ void mbar_wait(uint32_t mbar, uint32_t parity) {
    asm volatile(
        "{\n\t.reg .pred P;\n\t"
        "WL_%=:\n\t"
        "mbarrier.try_wait.parity.acquire.cta.shared::cta.b64 P, [%0], %1, 0x989680;\n\t"
        "@!P bra WL_%=;\n\t}"
        :: "r"(mbar), "r"(parity) : "memory");
}
__device__ __forceinline__ void bulk_g2s(uint32_t dst, const void* src, uint32_t mbar) {
    asm volatile(
        "cp.async.bulk.shared::cluster.global.mbarrier::complete_tx::bytes "
        "[%0], [%1], %2, [%3];"
        :: "r"(dst), "l"(src), "r"((uint32_t)BLOCK_BYTES), "r"(mbar) : "memory");
}
__device__ __forceinline__ void ldsm4(uint32_t* r, uint32_t a) {
    asm volatile("ldmatrix.sync.aligned.m8n8.x4.shared.b16 {%0,%1,%2,%3}, [%4];"
                 : "=r"(r[0]), "=r"(r[1]), "=r"(r[2]), "=r"(r[3]) : "r"(a));
}
// int8 k32 MMA: byte-layout identical to f16 k16 (16 rows x 32B fragments)
__device__ __forceinline__ void mma_s8(int* d, const uint32_t* a,
                                       uint32_t b0, uint32_t b1) {
    asm volatile(
        "mma.sync.aligned.m16n8k32.row.col.s32.s8.s8.s32 "
        "{%0,%1,%2,%3}, {%4,%5,%6,%7}, {%8,%9}, {%0,%1,%2,%3};"
        : "+r"(d[0]), "+r"(d[1]), "+r"(d[2]), "+r"(d[3])
        : "r"(a[0]), "r"(a[1]), "r"(a[2]), "r"(a[3]), "r"(b0), "r"(b1));
}
__device__ __forceinline__ int ldcg_i(const int* p) {
    int v; asm volatile("ld.global.cg.s32 %0, [%1];" : "=r"(v) : "l"(p)); return v;
}
#define SWZ(x) ((x) ^ ((((uint32_t)(x)) >> 3) & 0x70))

// SMEM layout (relative to 1024-aligned base)
#define SM_FULL   0           // 2 x 8B mbarriers
#define SM_EMPTY  64          // 2 x 8B mbarriers
#define SM_FLAG   128
#define SM_XXI    256         // 128 float
#define SM_LABI   768         // 128 int
#define SM_SCI    1280        // 128 float
#define SM_XXJ    1792        // 256 float
#define SM_LABJ   2816        // 256 int
#define SM_SCJ    3840        // 256 float
#define SM_STAGE  5120        // 2 stages x 96KB: A(32K) | B0(32K) | B1(32K)
#define STAGE_SZ  98304
#define SMEM_TOTAL (SM_STAGE + NSTG * STAGE_SZ + 1024)   // ~198KB -> 1 CTA/SM

// ---------------------------------------------------------------------------
// Prep: int8 quantize (per-row scale) into chunk-major PRE-SWIZZLED layout,
// exact fp32 norms, scales, labels, init. One warp per row.
// ---------------------------------------------------------------------------
__global__ void prep_kernel(const float* __restrict__ feat,
                            const int* __restrict__ lab_raw, int n) {
    int row  = blockIdx.x * 8 + (threadIdx.x >> 5);
    int lane = threadIdx.x & 31;
    if (row >= n) return;

    const float4* p = (const float4*)(feat + (size_t)row * DIMK);
    float4 v0 = p[2 * lane];          // cols lane*8 .. lane*8+3
    float4 v1 = p[2 * lane + 1];      // cols lane*8+4 .. lane*8+7

    float s = v0.x * v0.x + v0.y * v0.y + v0.z * v0.z + v0.w * v0.w
            + v1.x * v1.x + v1.y * v1.y + v1.z * v1.z + v1.w * v1.w;
    float m = fmaxf(fmaxf(fmaxf(fabsf(v0.x), fabsf(v0.y)), fmaxf(fabsf(v0.z), fabsf(v0.w))),
                    fmaxf(fmaxf(fabsf(v1.x), fabsf(v1.y)), fmaxf(fabsf(v1.z), fabsf(v1.w))));
#pragma unroll
    for (int o = 16; o; o >>= 1) {
        s += __shfl_xor_sync(0xffffffffu, s, o);
        m = fmaxf(m, __shfl_xor_sync(0xffffffffu, m, o));
    }
    const float inv = (m > 0.f) ? 127.f / m : 0.f;

    float vv[8] = {v0.x, v0.y, v0.z, v0.w, v1.x, v1.y, v1.z, v1.w};
    uint8_t qb[8];
#pragma unroll
    for (int k = 0; k < 8; k++) {
        int q = __float2int_rn(vv[k] * inv);
        q = max(-127, min(127, q));
        qb[k] = (uint8_t)(int8_t)q;
    }
    uint64_t pk;
    memcpy(&pk, qb, 8);

    const int blk = row >> 7;
    const int c   = lane >> 4;                 // sub-chunk = (lane*8)/128
    const uint32_t gr = SWZ(((uint32_t)(row & 127)) * 128 + (((lane & 15) >> 1) << 4))
                      + (uint32_t)(lane & 1) * 8;
    char* dst = (char*)g_i8s + (((size_t)blk * NSC + c) << 14) + gr;
    *(uint64_t*)dst = pk;

    if (lane == 0) {
        g_xx[row]     = s;
        g_sc[row]     = (m > 0.f) ? m / 127.f : 0.f;
        g_posmax[row] = 0;
        g_negmin[row] = __float_as_int(FLT_MAX);
    }
    if (lane == 1) {
        bool is64 = true;
#pragma unroll
        for (int i = 0; i < 32; i++)
            if (lab_raw[2 * i + 1] != 0) { is64 = false; break; }
        g_lab[row] = is64 ? lab_raw[2 * row] : lab_raw[row];
    }
    if (row == 0 && lane == 2) g_done = 0;
}

// ---------------------------------------------------------------------------
// Supertile enumeration: (ti, sj), sj covers j-blocks {2sj, 2sj+1}.
// Count = 272 for ntb=32. Duplicate transpose halves harmless (idempotent).
// ---------------------------------------------------------------------------
__device__ __forceinline__ void decode_st(int t, int nsb, int& ti, int& sj) {
    ti = 0;
    while (t >= nsb - (ti >> 1)) { t -= nsb - (ti >> 1); ti++; }
    sj = (ti >> 1) + t;
}

// Issue a whole supertile's operands (K=256): A + B0 + B1, three 32KB copies.
__device__ __forceinline__ void issue_supertile(uint32_t st, uint32_t fb,
                                                int ti, int sj) {
    MBAR_EXPECT_TX(fb, 3 * BLOCK_BYTES);
    const char* A  = (const char*)g_i8s + (((size_t)ti)           * NSC << 14);
    const char* B0 = (const char*)g_i8s + (((size_t)(2 * sj))     * NSC << 14);
    const char* B1 = (const char*)g_i8s + (((size_t)(2 * sj + 1)) * NSC << 14);
    bulk_g2s(st,                   A,  fb);
    bulk_g2s(st + BLOCK_BYTES,     B0, fb);
    bulk_g2s(st + 2 * BLOCK_BYTES, B1, fb);
}

// Full K=256 MMA for one supertile, per-warp 32x64 output (s32 acc).
// 8 uninterrupted k32-steps: 32 LDSM + 128 IMMA per warp, no mid-tile syncs.
__device__ __forceinline__ void mma_supertile(int acc[2][8][4], uint32_t st,
                                              int m_base, int n_base, int lane) {
    const uint32_t sA = st;
    const uint32_t sB = st + BLOCK_BYTES + ((uint32_t)(n_base >> 7)) * BLOCK_BYTES;
    const int nloc = n_base & 127;               // 0 or 64 within B block
#pragma unroll
    for (int ks = 0; ks < 8; ks++) {              // k32 steps over K=256
        const uint32_t so   = (uint32_t)(ks >> 2) * SUB_BYTES;
        const uint32_t koff = (uint32_t)(ks & 3) * 32 + ((lane >> 4) << 4);
        uint32_t a[2][4], b[4][4];
#pragma unroll
        for (int mt = 0; mt < 2; mt++) {
            uint32_t ad = SWZ((uint32_t)(m_base + mt * 16 + (lane & 15)) * 128 + koff);
            ldsm4(a[mt], sA + so + ad);
        }
#pragma unroll
        for (int p = 0; p < 4; p++) {
            uint32_t bd = SWZ((uint32_t)(nloc + p * 16 + (lane & 15)) * 128 + koff);
            ldsm4(b[p], sB + so + bd);
        }
#pragma unroll
        for (int mt = 0; mt < 2; mt++)
#pragma unroll
            for (int nt = 0; nt < 8; nt++) {
                const int p = nt >> 1, q = nt & 1;
                mma_s8(acc[mt][nt], a[mt], b[p][q], b[p][2 + q]);
            }
    }
}

// ---------------------------------------------------------------------------
// Persistent kernel: 128x256 supertiles, whole-supertile stages (K=256),
// 2-stage 96KB ring, ONE barrier wait per supertile, int8 scaled epilogue,
// fused final reduction.
// ---------------------------------------------------------------------------
__global__ void __launch_bounds__(NTHR, 1) tile_kernel(float* __restrict__ out, int n) {
    extern __shared__ char smem_raw[];
    uint32_t sb_raw = s2u(smem_raw);
    uint32_t pad = (1024u - (sb_raw & 1023u)) & 1023u;
    char* sm = smem_raw + pad;
    uint32_t sb = sb_raw + pad;

    float* xxi_s  = (float*)(sm + SM_XXI);
    int*   labi_s = (int*)(sm + SM_LABI);
    float* sci_s  = (float*)(sm + SM_SCI);
    float* xxj_s  = (float*)(sm + SM_XXJ);
    int*   labj_s = (int*)(sm + SM_LABJ);
    float* scj_s  = (float*)(sm + SM_SCJ);

    const int tid = threadIdx.x, lane = tid & 31, w = tid >> 5;
    const int m_base = (w & 3) * 32;     // 4 warps along M (128 rows)
    const int n_base = (w >> 2) * 64;    // 4 warps along N (256 cols)

    const int ntb = n >> 7;
    const int nsb = ntb >> 1;
    int ST = 0;
    for (int t2 = 0; t2 < ntb; t2++) ST += nsb - (t2 >> 1);
    const int G = (ST - (int)blockIdx.x + (int)gridDim.x - 1) / (int)gridDim.x;

    if (tid == 0) {
#pragma unroll
        for (int s = 0; s < NSTG; s++) {
            MBAR_INIT(sb + SM_FULL + s * 8, 1);
            MBAR_INIT(sb + SM_EMPTY + s * 8, 16);
        }
    }
    __syncthreads();

    if (G > 0) {
        int ti, sj;
        decode_st(blockIdx.x, nsb, ti, sj);
        if (tid == 0) {
            issue_supertile(sb + SM_STAGE, sb + SM_FULL, ti, sj);
            if (G > 1) {
                int t1, s1;
                decode_st((int)blockIdx.x + (int)gridDim.x, nsb, t1, s1);
                issue_supertile(sb + SM_STAGE + STAGE_SZ, sb + SM_FULL + 8, t1, s1);
            }
        }

        int acc[2][8][4];

        for (int g = 0; g < G; g++) {
            const int s = g & 1;
            if (g > 0) decode_st((int)blockIdx.x + g * (int)gridDim.x, nsb, ti, sj);

            // stage epilogue operands (overlaps in-flight TMA)
            __syncthreads();                       // prev epilogue done reading
            if (tid < 128) {
                xxi_s[tid]  = g_xx[ti * 128 + tid];
                labi_s[tid] = g_lab[ti * 128 + tid];
                sci_s[tid]  = g_sc[ti * 128 + tid];
            } else if (tid < 384) {
                int q = tid - 128;
                xxj_s[q]  = g_xx[sj * 256 + q];
                labj_s[q] = g_lab[sj * 256 + q];
                scj_s[q]  = g_sc[sj * 256 + q];
            }
            __syncthreads();
#pragma unroll
            for (int a = 0; a < 2; a++)
#pragma unroll
                for (int b = 0; b < 8; b++)
#pragma unroll
                    for (int e = 0; e < 4; e++) acc[a][b][e] = 0;

            // producer: refill the OTHER stage for supertile g+1 (G>2 only)
            if (tid == 0 && g >= 1 && g + 1 < G) {
                mbar_wait(sb + SM_EMPTY + (s ^ 1) * 8, (uint32_t)(((g - 1) >> 1) & 1));
                FENCE_ASYNC();
                int lti, lsj;
                decode_st((int)blockIdx.x + (g + 1) * (int)gridDim.x, nsb, lti, lsj);
                issue_supertile(sb + SM_STAGE + (s ^ 1) * STAGE_SZ,
                                sb + SM_FULL + (s ^ 1) * 8, lti, lsj);
            }

            mbar_wait(sb + SM_FULL + s * 8, (uint32_t)((g >> 1) & 1));
            mma_supertile(acc, sb + SM_STAGE + s * STAGE_SZ, m_base, n_base, lane);
            if (lane == 0) MBAR_ARRIVE(sb + SM_EMPTY + s * 8);

            // ---- epilogue: d^2 = xx_i + xx_j - 2 s_i s_j dotq ----
            float xi[4], m2si[4]; int li[4];
#pragma unroll
            for (int mt = 0; mt < 2; mt++)
#pragma unroll
                for (int rh = 0; rh < 2; rh++) {
                    int r = m_base + mt * 16 + (lane >> 2) + 8 * rh;
                    xi[mt * 2 + rh]   = xxi_s[r];
                    li[mt * 2 + rh]   = labi_s[r];
                    m2si[mt * 2 + rh] = -2.f * sci_s[r];
                }
            float xj[16], sjv[16]; int lj[16];
#pragma unroll
            for (int nt = 0; nt < 8; nt++)
#pragma unroll
                for (int cc = 0; cc < 2; cc++) {
                    int q = n_base + nt * 8 + (lane & 3) * 2 + cc;
                    xj[nt * 2 + cc]  = xxj_s[q];
                    lj[nt * 2 + cc]  = labj_s[q];
                    sjv[nt * 2 + cc] = scj_s[q];
                }
            float d2v[2][8][4];
#pragma unroll
            for (int mt = 0; mt < 2; mt++)
#pragma unroll
                for (int nt = 0; nt < 8; nt++)
#pragma unroll
                    for (int e = 0; e < 4; e++) {
                        int rh = e >> 1, cc = e & 1;
                        d2v[mt][nt][e] = fmaf(m2si[mt * 2 + rh] * sjv[nt * 2 + cc],
                                              (float)acc[mt][nt][e],
                                              xi[mt * 2 + rh] + xj[nt * 2 + cc]);
                    }

            // row direction
#pragma unroll
            for (int mt = 0; mt < 2; mt++)
#pragma unroll
                for (int rh = 0; rh < 2; rh++) {
                    float pm = -1.f, nm = FLT_MAX;
                    const int L = li[mt * 2 + rh];
#pragma unroll
                    for (int nt = 0; nt < 8; nt++)
#pragma unroll
                        for (int cc = 0; cc < 2; cc++) {
                            float v = d2v[mt][nt][rh * 2 + cc];
                            if (L == lj[nt * 2 + cc]) pm = fmaxf(pm, v);
                            else                      nm = fminf(nm, v);
                        }
                    pm = fmaxf(pm, __shfl_xor_sync(0xffffffffu, pm, 1));
                    pm = fmaxf(pm, __shfl_xor_sync(0xffffffffu, pm, 2));
                    nm = fminf(nm, __shfl_xor_sync(0xffffffffu, nm, 1));
                    nm = fminf(nm, __shfl_xor_sync(0xffffffffu, nm, 2));
                    if ((lane & 3) == 0) {
                        int gi = ti * 128 + m_base + mt * 16 + (lane >> 2) + 8 * rh;
                        atomicMax(&g_posmax[gi], __float_as_int(pm));
                        atomicMin(&g_negmin[gi], __float_as_int(nm));
                    }
                }

            // column direction (symmetry)
#pragma unroll
            for (int nt = 0; nt < 8; nt++)
#pragma unroll
                for (int cc = 0; cc < 2; cc++) {
                    float pm = -1.f, nm = FLT_MAX;
                    const int L = lj[nt * 2 + cc];
#pragma unroll
                    for (int mt = 0; mt < 2; mt++)
#pragma unroll
                        for (int rh = 0; rh < 2; rh++) {
                            float v = d2v[mt][nt][rh * 2 + cc];
                            if (L == li[mt * 2 + rh]) pm = fmaxf(pm, v);
                            else                      nm = fminf(nm, v);
                        }
                    pm = fmaxf(pm, __shfl_xor_sync(0xffffffffu, pm, 4));
                    pm = fmaxf(pm, __shfl_xor_sync(0xffffffffu, pm, 8));
                    pm = fmaxf(pm, __shfl_xor_sync(0xffffffffu, pm, 16));
                    nm = fminf(nm, __shfl_xor_sync(0xffffffffu, nm, 4));
                    nm = fminf(nm, __shfl_xor_sync(0xffffffffu, nm, 8));
                    nm = fminf(nm, __shfl_xor_sync(0xffffffffu, nm, 16));
                    if (lane < 4) {
                        int gj = sj * 256 + n_base + nt * 8 + (lane & 3) * 2 + cc;
                        atomicMax(&g_posmax[gj], __float_as_int(pm));
                        atomicMin(&g_negmin[gj], __float_as_int(nm));
                    }
                }
        }
    }

    // ---- completion counter: last CTA performs the finalize reduction ----
    __syncthreads();
    if (tid == 0) {
        __threadfence();
        int prev = atomicAdd(&g_done, 1);
        *(volatile int*)(sm + SM_FLAG) = (prev == (int)gridDim.x - 1) ? 1 : 0;
    }
    __syncthreads();
    if (*(volatile int*)(sm + SM_FLAG)) {
        float* ss = (float*)(sm + SM_STAGE);
        float* sc = ss + NTHR;
        float sum = 0.f, cnt = 0.f;
        for (int i = tid; i < n; i += NTHR) {
            float ap2 = __int_as_float(ldcg_i(&g_posmax[i]));
            float ap  = sqrtf(fmaxf(ap2, 1e-12f));
            float nm2 = __int_as_float(ldcg_i(&g_negmin[i]));
            bool  has_neg = nm2 < 1e30f;
            float an  = has_neg ? sqrtf(fmaxf(nm2, 1e-12f)) : 0.f;
            bool  valid = (ap < 1000000.0f) && (an > 0.f);
            if (valid) {
                sum += fmaxf(0.3f + ap - an, 0.f);
                cnt += 1.f;
            }
        }
        ss[tid] = sum;
        sc[tid] = cnt;
        __syncthreads();
        for (int o = NTHR / 2; o; o >>= 1) {
            if (tid < o) {
                ss[tid] += ss[tid + o];
                sc[tid] += sc[tid + o];
            }
            __syncthreads();
        }
        if (tid == 0)
            out[0] = (sc[0] > 0.f) ? ss[0] / fmaxf(sc[0], 1.f) : 0.f;
    }
}

// ---------------------------------------------------------------------------
extern "C" void kernel_launch(void* const* d_in, const int* in_sizes, int n_in,
                              void* d_out, int out_size) {
    const float* feat   = (const float*)d_in[0];
    const int*   labels = (const int*)d_in[1];   // int32/int64 auto-detected
    int n = in_sizes[1];                         // 4096

    cudaFuncSetAttribute(tile_kernel, cudaFuncAttributeMaxDynamicSharedMemorySize,
                         SMEM_TOTAL);

    prep_kernel<<<(n + 7) / 8, 256>>>(feat, labels, n);
    tile_kernel<<<148, NTHR, SMEM_TOTAL>>>((float*)d_out, n);
}